// round 9
// baseline (speedup 1.0000x reference)
#include <cuda_runtime.h>
#include <cuda_fp16.h>
#include <cstdint>

// Problem constants
#define NB 1024
#define NN 256
#define FF 63
#define DD 64

// smem byte offsets (single CTA of 512 threads per SM)
#define OFF_VH   0        // half Vh[256][72]                 36864 B
#define OFF_WHI  36864    // half Whi[64][136] (rel|root)     17408 B
#define OFF_RING 54272    // fp32 ring: 16 warps x 4 stages x 2048 B = 131072 B
#define OFF_CVT  185344   // half cvt buf: 16 warps x 1280 B  = 20480 B
#define OFF_B1   205824   // float[64]
#define OFF_A0   206080   // float[256] adj row 0
#define OFF_PART 207104   // float[16][64] per-warp SA partials
#define OFF_X0   211200   // float[64] x row 0
#define OFF_SA   211456   // float[64]
#define OFF_SB   211712   // float[64]
#define SMEM_BYTES 211968

__device__ __forceinline__ uint32_t smem_u32(const void* p) {
    return (uint32_t)__cvta_generic_to_shared(p);
}

__device__ __forceinline__ void ldsm_x4(uint32_t addr, uint32_t& r0, uint32_t& r1,
                                        uint32_t& r2, uint32_t& r3) {
    asm volatile("ldmatrix.sync.aligned.m8n8.x4.shared.b16 {%0,%1,%2,%3}, [%4];"
                 : "=r"(r0), "=r"(r1), "=r"(r2), "=r"(r3) : "r"(addr));
}

__device__ __forceinline__ void ldsm_x4t(uint32_t addr, uint32_t& r0, uint32_t& r1,
                                         uint32_t& r2, uint32_t& r3) {
    asm volatile("ldmatrix.sync.aligned.m8n8.x4.trans.shared.b16 {%0,%1,%2,%3}, [%4];"
                 : "=r"(r0), "=r"(r1), "=r"(r2), "=r"(r3) : "r"(addr));
}

__device__ __forceinline__ void mma16816(float* d, uint32_t a0, uint32_t a1,
                                         uint32_t a2, uint32_t a3,
                                         uint32_t b0, uint32_t b1) {
    asm volatile(
        "mma.sync.aligned.m16n8k16.row.col.f32.f16.f16.f32 "
        "{%0,%1,%2,%3}, {%4,%5,%6,%7}, {%8,%9}, {%0,%1,%2,%3};"
        : "+f"(d[0]), "+f"(d[1]), "+f"(d[2]), "+f"(d[3])
        : "r"(a0), "r"(a1), "r"(a2), "r"(a3), "r"(b0), "r"(b1));
}

#define CP_ASYNC16(dst, src) \
    asm volatile("cp.async.cg.shared.global [%0], [%1], 16;" \
                 :: "r"(dst), "l"(src) : "memory")
#define CP_COMMIT() asm volatile("cp.async.commit_group;" ::: "memory")
#define CP_WAIT(n)  asm volatile("cp.async.wait_group %0;" :: "n"(n) : "memory")

__global__ void __launch_bounds__(512, 1) gnn_fused_kernel(
    const float* __restrict__ adj, const float* __restrict__ vec,
    const float* __restrict__ w1_rel, const float* __restrict__ w1_root,
    const float* __restrict__ b1,
    const float* __restrict__ w2_rel, const float* __restrict__ w2_root,
    const float* __restrict__ b2,
    const float* __restrict__ wf, const float* __restrict__ bf,
    float* __restrict__ out)
{
    extern __shared__ char smem[];
    __half* Vh   = (__half*)(smem + OFF_VH);
    __half* Whi  = (__half*)(smem + OFF_WHI);
    float*  B1s  = (float*)(smem + OFF_B1);
    float*  A0s  = (float*)(smem + OFF_A0);
    float*  PART = (float*)(smem + OFF_PART);
    float*  X0s  = (float*)(smem + OFF_X0);
    float*  SAs  = (float*)(smem + OFF_SA);
    float*  SBs  = (float*)(smem + OFF_SB);

    const int tid  = threadIdx.x;
    const int lane = tid & 31;
    const int wid  = tid >> 5;
    const int b    = blockIdx.x;

    const int row16 = lane & 15;
    const int half8 = (lane >> 4) << 3;  // 0 or 8
    const int mb = wid * 16;             // 16 warps x 16 rows

    char*   ring = smem + OFF_RING + wid * 8192;      // 4 stages x 2048 B
    __half* cvt  = (__half*)(smem + OFF_CVT + wid * 1280);  // 16 x 40 halves

    const float* abf = adj + (size_t)b * (NN * NN);

    // copy-lane mapping: 4 iters x 32 lanes = 128 chunks of 16B per stage
    const int crow0 = lane >> 3;      // + it*4
    const int cch   = lane & 7;       // 16B chunk within 32-float row

    // issue one cp.async stage: 16 rows x 32 floats of adj (k-cols s*32..s*32+31)
#define ISSUE_STAGE(s)                                                        \
    do {                                                                      \
        char* slotp = ring + (((s) & 3) << 11);                               \
        _Pragma("unroll")                                                     \
        for (int it = 0; it < 4; ++it) {                                      \
            int row = crow0 + it * 4;                                         \
            uint32_t dst = smem_u32(slotp + (row * 32 + cch * 4) * 4);        \
            const float* src = abf + (size_t)(mb + row) * NN + (s) * 32 +     \
                               cch * 4;                                       \
            CP_ASYNC16(dst, src);                                             \
        }                                                                     \
        CP_COMMIT();                                                          \
    } while (0)

    // -------- prologue: 3 stages in flight before Phase A --------------------
    ISSUE_STAGE(0);
    ISSUE_STAGE(1);
    ISSUE_STAGE(2);

    // ---------------- Phase A: load Vh (fp16) + Whi weights + misc ------------
    {
        const float4* v4 = (const float4*)(vec + (size_t)b * (NN * FF));
        for (int p = tid; p < (NN * FF) / 4; p += 512) {
            float4 x = v4[p];
            float comp[4] = {x.x, x.y, x.z, x.w};
            int idx = p * 4;
#pragma unroll
            for (int q = 0; q < 4; ++q) {
                int ii = idx + q;
                int r = ii / FF, c = ii - r * FF;
                Vh[r * 72 + c] = __float2half(comp[q]);
            }
        }
        if (tid < NN) Vh[tid * 72 + 63] = __float2half(0.0f);  // zero pad col 63

        for (int idx = tid; idx < FF * DD; idx += 512) {
            int k = idx >> 6, n = idx & 63;
            Whi[k * 136 + n]      = __float2half(w1_rel[idx]);
            Whi[k * 136 + 64 + n] = __float2half(w1_root[idx]);
        }
        if (tid < 128) Whi[63 * 136 + tid] = __float2half(0.0f);  // pad k=63
        if (tid < 64) B1s[tid] = b1[tid];
        if (tid < NN) A0s[tid] = abf[tid];
    }
    __syncthreads();

    // ------- Phase B: T = adj @ Vh (exact), cp.async ring, 8 k-steps of 32 -----
    float accT[8][4];
#pragma unroll
    for (int q = 0; q < 8; ++q)
#pragma unroll
        for (int t = 0; t < 4; ++t) accT[q][t] = 0.0f;

#pragma unroll
    for (int s = 0; s < 8; ++s) {
        if (s <= 5)      CP_WAIT(2);
        else if (s == 6) CP_WAIT(1);
        else             CP_WAIT(0);
        __syncwarp();
        if (s < 5) ISSUE_STAGE(s + 3);

        // read stage s (fp32), convert, store fp16 to cvt buffer
        const float* slot = (const float*)(ring + ((s & 3) << 11));
        float4 v[4];
#pragma unroll
        for (int it = 0; it < 4; ++it) {
            int row = crow0 + it * 4;
            v[it] = *(const float4*)(slot + row * 32 + cch * 4);
        }
#pragma unroll
        for (int it = 0; it < 4; ++it) {
            int row = crow0 + it * 4;
            union { half2 h[2]; uint2 u; } pk;
            pk.h[0] = __floats2half2_rn(v[it].x, v[it].y);
            pk.h[1] = __floats2half2_rn(v[it].z, v[it].w);
            *(uint2*)&cvt[row * 40 + cch * 4] = pk.u;
        }
        __syncwarp();

#pragma unroll
        for (int kh = 0; kh < 2; ++kh) {
            uint32_t a0, a1, a2, a3;
            ldsm_x4(smem_u32(&cvt[row16 * 40 + kh * 16 + half8]), a0, a1, a2, a3);
            const int krow = s * 32 + kh * 16 + row16;
#pragma unroll
            for (int j = 0; j < 4; ++j) {
                uint32_t b0, b1r, b2r, b3r;
                ldsm_x4t(smem_u32(&Vh[krow * 72 + j * 16 + half8]),
                         b0, b1r, b2r, b3r);
                mma16816(accT[2 * j],     a0, a1, a2, a3, b0, b1r);
                mma16816(accT[2 * j + 1], a0, a1, a2, a3, b2r, b3r);
            }
        }
        __syncwarp();  // cvt write-after-read guard for next step
    }

    // ------- stage Thi (16 rows x 64 cols fp16, stride 72) in ring area --------
    __half* thi = (__half*)ring;
    {
        const int rloc = lane >> 2;
        const int c0   = (lane & 3) * 2;
#pragma unroll
        for (int q = 0; q < 8; ++q) {
            const int c = q * 8 + c0;
            *(half2*)&thi[rloc * 72 + c] = __halves2half2(
                __float2half_rn(accT[q][0]), __float2half_rn(accT[q][1]));
            *(half2*)&thi[(rloc + 8) * 72 + c] = __halves2half2(
                __float2half_rn(accT[q][2]), __float2half_rn(accT[q][3]));
        }
        __syncwarp();
    }

    // ------- Phase C: accX = Vh@Whi_root + Thi@Whi_rel (2 pass-sets) -----------
    float accX[8][4];
#pragma unroll
    for (int q = 0; q < 8; ++q)
#pragma unroll
        for (int t = 0; t < 4; ++t) accX[q][t] = 0.0f;

    {
        uint32_t af[4][4];
        // root term: A = Vh own rows
#pragma unroll
        for (int ks = 0; ks < 4; ++ks)
            ldsm_x4(smem_u32(&Vh[(mb + row16) * 72 + ks * 16 + half8]),
                    af[ks][0], af[ks][1], af[ks][2], af[ks][3]);
#pragma unroll
        for (int ks = 0; ks < 4; ++ks)
#pragma unroll
            for (int nt = 0; nt < 4; ++nt) {
                uint32_t b0, b1r, b2r, b3r;
                ldsm_x4t(smem_u32(
                    &Whi[(ks * 16 + row16) * 136 + 64 + nt * 16 + half8]),
                    b0, b1r, b2r, b3r);
                mma16816(accX[2 * nt],     af[ks][0], af[ks][1], af[ks][2],
                         af[ks][3], b0, b1r);
                mma16816(accX[2 * nt + 1], af[ks][0], af[ks][1], af[ks][2],
                         af[ks][3], b2r, b3r);
            }

        // rel term: A = Thi
#pragma unroll
        for (int ks = 0; ks < 4; ++ks)
            ldsm_x4(smem_u32(&thi[row16 * 72 + ks * 16 + half8]),
                    af[ks][0], af[ks][1], af[ks][2], af[ks][3]);
#pragma unroll
        for (int ks = 0; ks < 4; ++ks)
#pragma unroll
            for (int nt = 0; nt < 4; ++nt) {
                uint32_t b0, b1r, b2r, b3r;
                ldsm_x4t(smem_u32(&Whi[(ks * 16 + row16) * 136 + nt * 16 + half8]),
                         b0, b1r, b2r, b3r);
                mma16816(accX[2 * nt],     af[ks][0], af[ks][1], af[ks][2],
                         af[ks][3], b0, b1r);
                mma16816(accX[2 * nt + 1], af[ks][0], af[ks][1], af[ks][2],
                         af[ks][3], b2r, b3r);
            }

        // ---- epilogue: x = relu(accX+b1); fold node-0 readout in registers ----
        const int rloc = lane >> 2;
        const int c0   = (lane & 3) * 2;
        const int r0 = mb + rloc;
        const float a0lo = A0s[r0];
        const float a0hi = A0s[r0 + 8];
        float part[16];
#pragma unroll
        for (int q = 0; q < 8; ++q) {
            const int c = q * 8 + c0;
            float2 bb = *(float2*)&B1s[c];
            float x00 = fmaxf(accX[q][0] + bb.x, 0.0f);
            float x01 = fmaxf(accX[q][1] + bb.y, 0.0f);
            float x80 = fmaxf(accX[q][2] + bb.x, 0.0f);
            float x81 = fmaxf(accX[q][3] + bb.y, 0.0f);
            part[2 * q]     = a0lo * x00 + a0hi * x80;
            part[2 * q + 1] = a0lo * x01 + a0hi * x81;
            if (wid == 0 && rloc == 0) {   // x row 0 lives in lanes 0-3 of warp 0
                X0s[c]     = x00;
                X0s[c + 1] = x01;
            }
        }
        // reduce over the 8 row-groups (lanes differing in bits 2..4)
#pragma unroll
        for (int off = 4; off <= 16; off <<= 1)
#pragma unroll
            for (int t = 0; t < 16; ++t)
                part[t] += __shfl_xor_sync(0xffffffffu, part[t], off);
        if (lane < 4) {
#pragma unroll
            for (int q = 0; q < 8; ++q) {
                PART[wid * 64 + q * 8 + c0]     = part[2 * q];
                PART[wid * 64 + q * 8 + c0 + 1] = part[2 * q + 1];
            }
        }
    }
    __syncthreads();

    // ---------------- Final head: layer 2 at node 0 + linear head --------------
    if (tid < 64) {
        float s = 0.0f;
#pragma unroll
        for (int w = 0; w < 16; ++w) s += PART[w * 64 + tid];
        SAs[tid] = s;   // SA = adj[0,:] @ x
    }
    __syncthreads();
    if (tid < 64) {
        float acc = b2[tid];
#pragma unroll 8
        for (int d = 0; d < 64; ++d)
            acc += SAs[d] * w2_rel[d * 64 + tid] + X0s[d] * w2_root[d * 64 + tid];
        float y = fmaxf(acc, 0.0f);
        SBs[tid] = y + X0s[tid];  // x0 + y0
    }
    __syncthreads();
    if (tid < 2) {
        float s = bf[tid];
#pragma unroll 16
        for (int d = 0; d < 64; ++d) s = fmaf(SBs[d], wf[d * 2 + tid], s);
        out[(size_t)b * 2 + tid] = s;
    }
#undef ISSUE_STAGE
}

extern "C" void kernel_launch(void* const* d_in, const int* in_sizes, int n_in,
                              void* d_out, int out_size) {
    const float* adj     = (const float*)d_in[0];
    const float* vec     = (const float*)d_in[1];
    const float* w1_rel  = (const float*)d_in[2];
    const float* w1_root = (const float*)d_in[3];
    const float* b1      = (const float*)d_in[4];
    const float* w2_rel  = (const float*)d_in[5];
    const float* w2_root = (const float*)d_in[6];
    const float* b2      = (const float*)d_in[7];
    const float* wf      = (const float*)d_in[8];
    const float* bf      = (const float*)d_in[9];
    float* out = (float*)d_out;

    cudaFuncSetAttribute(gnn_fused_kernel,
                         cudaFuncAttributeMaxDynamicSharedMemorySize, SMEM_BYTES);
    gnn_fused_kernel<<<NB, 512, SMEM_BYTES>>>(
        adj, vec, w1_rel, w1_root, b1, w2_rel, w2_root, b2, wf, bf, out);
}

// round 10
// speedup vs baseline: 1.4993x; 1.4993x over previous
#include <cuda_runtime.h>
#include <cuda_fp16.h>
#include <cstdint>

// Problem constants
#define NB 1024
#define NN 256
#define FF 63
#define DD 64

// smem byte offsets
#define OFF_VH   0        // half Vh[256][72]                 36864 B
#define OFF_WHI  36864    // half Whi[64][136] (rel|root)     17408 B
#define OFF_PF   54272    // float Pf[256][136]              139264 B (c0-63 Hrel, c64-127 Hroot)
#define OFF_B1   193536   // float[64]
#define OFF_A0   193792   // float[256] adj row 0
#define OFF_JL   194816   // int[256] needed-row indices
#define OFF_VL   195840   // float[256] adj[0,j] values
#define OFF_CNT  196864   // int (padded)
#define OFF_PART 196992   // float[16][64] per-warp SA partials
#define OFF_X0   201088   // float[64] x row 0
#define OFF_SA   201344   // float[64]
#define OFF_SB   201600   // float[64]
#define SMEM_BYTES 201856

__device__ __forceinline__ uint32_t smem_u32(const void* p) {
    return (uint32_t)__cvta_generic_to_shared(p);
}

__device__ __forceinline__ void ldsm_x4(uint32_t addr, uint32_t& r0, uint32_t& r1,
                                        uint32_t& r2, uint32_t& r3) {
    asm volatile("ldmatrix.sync.aligned.m8n8.x4.shared.b16 {%0,%1,%2,%3}, [%4];"
                 : "=r"(r0), "=r"(r1), "=r"(r2), "=r"(r3) : "r"(addr));
}

__device__ __forceinline__ void ldsm_x4t(uint32_t addr, uint32_t& r0, uint32_t& r1,
                                         uint32_t& r2, uint32_t& r3) {
    asm volatile("ldmatrix.sync.aligned.m8n8.x4.trans.shared.b16 {%0,%1,%2,%3}, [%4];"
                 : "=r"(r0), "=r"(r1), "=r"(r2), "=r"(r3) : "r"(addr));
}

__device__ __forceinline__ void mma16816(float* d, uint32_t a0, uint32_t a1,
                                         uint32_t a2, uint32_t a3,
                                         uint32_t b0, uint32_t b1) {
    asm volatile(
        "mma.sync.aligned.m16n8k16.row.col.f32.f16.f16.f32 "
        "{%0,%1,%2,%3}, {%4,%5,%6,%7}, {%8,%9}, {%0,%1,%2,%3};"
        : "+f"(d[0]), "+f"(d[1]), "+f"(d[2]), "+f"(d[3])
        : "r"(a0), "r"(a1), "r"(a2), "r"(a3), "r"(b0), "r"(b1));
}

__device__ __forceinline__ float4 ldcs4(const float4* p) {
    float4 v;
    asm volatile("ld.global.cs.v4.f32 {%0,%1,%2,%3}, [%4];"
                 : "=f"(v.x), "=f"(v.y), "=f"(v.z), "=f"(v.w) : "l"(p));
    return v;
}

__global__ void __launch_bounds__(512, 1) gnn_fused_kernel(
    const float* __restrict__ adj, const float* __restrict__ vec,
    const float* __restrict__ w1_rel, const float* __restrict__ w1_root,
    const float* __restrict__ b1,
    const float* __restrict__ w2_rel, const float* __restrict__ w2_root,
    const float* __restrict__ b2,
    const float* __restrict__ wf, const float* __restrict__ bf,
    float* __restrict__ out)
{
    extern __shared__ char smem[];
    __half* Vh   = (__half*)(smem + OFF_VH);
    __half* Whi  = (__half*)(smem + OFF_WHI);
    float*  Pf   = (float*)(smem + OFF_PF);
    float*  B1s  = (float*)(smem + OFF_B1);
    float*  A0s  = (float*)(smem + OFF_A0);
    int*    JL   = (int*)(smem + OFF_JL);
    float*  VL   = (float*)(smem + OFF_VL);
    int*    CNT  = (int*)(smem + OFF_CNT);
    float*  PART = (float*)(smem + OFF_PART);
    float*  X0s  = (float*)(smem + OFF_X0);
    float*  SAs  = (float*)(smem + OFF_SA);
    float*  SBs  = (float*)(smem + OFF_SB);

    const int tid  = threadIdx.x;
    const int lane = tid & 31;
    const int wid  = tid >> 5;
    const int b    = blockIdx.x;

    const float* abf = adj + (size_t)b * (NN * NN);

    // ---------------- Phase A: load Vh (fp16) + W1 (fp16) + misc --------------
    {
        const float4* v4 = (const float4*)(vec + (size_t)b * (NN * FF));
        for (int p = tid; p < (NN * FF) / 4; p += 512) {
            float4 x = ldcs4(&v4[p]);
            float comp[4] = {x.x, x.y, x.z, x.w};
            int idx = p * 4;
#pragma unroll
            for (int q = 0; q < 4; ++q) {
                int ii = idx + q;
                int r = ii / FF, c = ii - r * FF;
                Vh[r * 72 + c] = __float2half(comp[q]);
            }
        }
        if (tid < NN) Vh[tid * 72 + 63] = __float2half(0.0f);  // zero pad col 63

        for (int idx = tid; idx < FF * DD; idx += 512) {
            int k = idx >> 6, n = idx & 63;
            Whi[k * 136 + n]      = __float2half(w1_rel[idx]);
            Whi[k * 136 + 64 + n] = __float2half(w1_root[idx]);
        }
        if (tid < 128) Whi[63 * 136 + tid] = __float2half(0.0f);  // pad k=63
        if (tid < 64) B1s[tid] = b1[tid];
        if (tid < NN) A0s[tid] = abf[tid];
    }
    __syncthreads();

    const int row16 = lane & 15;
    const int half8 = (lane >> 4) << 3;  // 0 or 8
    const int mb = wid * 16;             // 16 warps x 16 rows

    // warp 15: build needed-row list from adj row 0 (before its projection work)
    if (wid == 15) {
        int base = 0;
#pragma unroll
        for (int e = 0; e < 8; ++e) {
            float v = A0s[e * 32 + lane];
            unsigned m = __ballot_sync(0xffffffffu, v != 0.0f);
            if (v != 0.0f) {
                int pos = base + __popc(m & ((1u << lane) - 1));
                JL[pos] = e * 32 + lane;
                VL[pos] = v;
            }
            base += __popc(m);
        }
        if (lane == 0) *CNT = base;
    }

    // ------- Projection: P[256][128] = Vh @ [w1_rel | w1_root], fp32 to smem ---
    {
        float acc[16][4];
#pragma unroll
        for (int q = 0; q < 16; ++q)
#pragma unroll
            for (int t = 0; t < 4; ++t) acc[q][t] = 0.0f;

#pragma unroll
        for (int kt = 0; kt < 4; ++kt) {
            uint32_t a0, a1, a2, a3;
            ldsm_x4(smem_u32(&Vh[(mb + row16) * 72 + kt * 16 + half8]),
                    a0, a1, a2, a3);
#pragma unroll
            for (int nt = 0; nt < 8; ++nt) {
                uint32_t b0, b1r, b2r, b3r;
                ldsm_x4t(smem_u32(&Whi[(kt * 16 + row16) * 136 + nt * 16 + half8]),
                         b0, b1r, b2r, b3r);
                mma16816(acc[2 * nt],     a0, a1, a2, a3, b0, b1r);
                mma16816(acc[2 * nt + 1], a0, a1, a2, a3, b2r, b3r);
            }
        }
        const int r0 = mb + (lane >> 2);
        const int c0 = (lane & 3) * 2;
#pragma unroll
        for (int q = 0; q < 16; ++q) {
            *(float2*)&Pf[r0 * 136 + q * 8 + c0] =
                make_float2(acc[q][0], acc[q][1]);
            *(float2*)&Pf[(r0 + 8) * 136 + q * 8 + c0] =
                make_float2(acc[q][2], acc[q][3]);
        }
    }
    __syncthreads();

    // ------- Phase G: gather only the needed adj rows, exact sparse x ----------
    {
        const int cnt = *CNT;
        float px = 0.0f, py = 0.0f;   // per-warp SA partial (cols 2*lane, 2*lane+1)

        for (int slot = wid; slot < cnt; slot += 16) {
            const int   j   = JL[slot];
            const float a0v = VL[slot];

            const float4* rowp = (const float4*)(abf + (size_t)j * NN);
            float4 va = ldcs4(&rowp[lane]);
            float4 vb = ldcs4(&rowp[32 + lane]);

            float accx = 0.0f, accy = 0.0f;
            float vals[8] = {va.x, va.y, va.z, va.w, vb.x, vb.y, vb.z, vb.w};
#pragma unroll
            for (int e = 0; e < 8; ++e) {
                float v = vals[e];
                unsigned m = __ballot_sync(0xffffffffu, v != 0.0f);
                while (m) {
                    int l = __ffs(m) - 1;
                    m &= m - 1;
                    float vv = __shfl_sync(0xffffffffu, v, l);
                    int kk = (e < 4) ? (l * 4 + e) : (128 + l * 4 + (e - 4));
                    const float2 h = *(const float2*)&Pf[kk * 136 + 2 * lane];
                    accx = fmaf(vv, h.x, accx);
                    accy = fmaf(vv, h.y, accy);
                }
            }
            // x[j] = relu(agg + Hroot[j] + b1)
            float xv0 = fmaxf(accx + Pf[j * 136 + 64 + 2 * lane] + B1s[2 * lane],
                              0.0f);
            float xv1 = fmaxf(accy + Pf[j * 136 + 64 + 2 * lane + 1] +
                              B1s[2 * lane + 1], 0.0f);
            px = fmaf(a0v, xv0, px);
            py = fmaf(a0v, xv1, py);
            if (j == 0) {
                X0s[2 * lane]     = xv0;
                X0s[2 * lane + 1] = xv1;
            }
        }
        PART[wid * 64 + 2 * lane]     = px;
        PART[wid * 64 + 2 * lane + 1] = py;
    }
    __syncthreads();

    // ---------------- Final head: layer 2 at node 0 + linear head --------------
    if (tid < 64) {
        float s = 0.0f;
#pragma unroll
        for (int w = 0; w < 16; ++w) s += PART[w * 64 + tid];
        SAs[tid] = s;   // SA = adj[0,:] @ x
    }
    __syncthreads();
    if (tid < 64) {
        float acc = b2[tid];
#pragma unroll 8
        for (int d = 0; d < 64; ++d)
            acc += SAs[d] * w2_rel[d * 64 + tid] + X0s[d] * w2_root[d * 64 + tid];
        float y = fmaxf(acc, 0.0f);
        SBs[tid] = y + X0s[tid];  // x0 + y0
    }
    __syncthreads();
    if (tid < 2) {
        float s = bf[tid];
#pragma unroll 16
        for (int d = 0; d < 64; ++d) s = fmaf(SBs[d], wf[d * 2 + tid], s);
        out[(size_t)b * 2 + tid] = s;
    }
}

extern "C" void kernel_launch(void* const* d_in, const int* in_sizes, int n_in,
                              void* d_out, int out_size) {
    const float* adj     = (const float*)d_in[0];
    const float* vec     = (const float*)d_in[1];
    const float* w1_rel  = (const float*)d_in[2];
    const float* w1_root = (const float*)d_in[3];
    const float* b1      = (const float*)d_in[4];
    const float* w2_rel  = (const float*)d_in[5];
    const float* w2_root = (const float*)d_in[6];
    const float* b2      = (const float*)d_in[7];
    const float* wf      = (const float*)d_in[8];
    const float* bf      = (const float*)d_in[9];
    float* out = (float*)d_out;

    cudaFuncSetAttribute(gnn_fused_kernel,
                         cudaFuncAttributeMaxDynamicSharedMemorySize, SMEM_BYTES);
    gnn_fused_kernel<<<NB, 512, SMEM_BYTES>>>(
        adj, vec, w1_rel, w1_root, b1, w2_rel, w2_root, b2, wf, bf, out);
}

// round 11
// speedup vs baseline: 1.9051x; 1.2707x over previous
#include <cuda_runtime.h>
#include <cuda_fp16.h>
#include <cstdint>

// Problem constants
#define NB 1024
#define NN 256
#define FF 63
#define DD 64

// smem byte offsets (2 CTAs resident per SM)
#define OFF_VH    0        // half Vh[256][72]              36864 B
#define OFF_WR    36864    // half Wr[64][72]  (w1_rel)      9216 B
#define OFF_WROOT 46080    // float Wroot[64][64] (w1_root) 16384 B
#define OFF_H     62464    // half Hrel[256][72]            36864 B
#define OFF_VBUF  99328    // float vbuf[8 warps][64]        2048 B
#define OFF_B1    101376   // float[64]
#define OFF_JL    101632   // int[128]
#define OFF_VL    102144   // float[128]
#define OFF_CNT   102656   // int (padded 128)
#define OFF_PART  102784   // float[8][64]
#define OFF_X0    104832   // float[64]
#define OFF_SA    105088   // float[64]
#define OFF_SB    105344   // float[64]
#define SMEM_BYTES 105600

__device__ __forceinline__ uint32_t smem_u32(const void* p) {
    return (uint32_t)__cvta_generic_to_shared(p);
}

__device__ __forceinline__ void ldsm_x4(uint32_t addr, uint32_t& r0, uint32_t& r1,
                                        uint32_t& r2, uint32_t& r3) {
    asm volatile("ldmatrix.sync.aligned.m8n8.x4.shared.b16 {%0,%1,%2,%3}, [%4];"
                 : "=r"(r0), "=r"(r1), "=r"(r2), "=r"(r3) : "r"(addr));
}

__device__ __forceinline__ void ldsm_x4t(uint32_t addr, uint32_t& r0, uint32_t& r1,
                                         uint32_t& r2, uint32_t& r3) {
    asm volatile("ldmatrix.sync.aligned.m8n8.x4.trans.shared.b16 {%0,%1,%2,%3}, [%4];"
                 : "=r"(r0), "=r"(r1), "=r"(r2), "=r"(r3) : "r"(addr));
}

__device__ __forceinline__ void mma16816(float* d, uint32_t a0, uint32_t a1,
                                         uint32_t a2, uint32_t a3,
                                         uint32_t b0, uint32_t b1) {
    asm volatile(
        "mma.sync.aligned.m16n8k16.row.col.f32.f16.f16.f32 "
        "{%0,%1,%2,%3}, {%4,%5,%6,%7}, {%8,%9}, {%0,%1,%2,%3};"
        : "+f"(d[0]), "+f"(d[1]), "+f"(d[2]), "+f"(d[3])
        : "r"(a0), "r"(a1), "r"(a2), "r"(a3), "r"(b0), "r"(b1));
}

__device__ __forceinline__ float4 ldcs4(const float4* p) {
    float4 v;
    asm volatile("ld.global.cs.v4.f32 {%0,%1,%2,%3}, [%4];"
                 : "=f"(v.x), "=f"(v.y), "=f"(v.z), "=f"(v.w) : "l"(p));
    return v;
}

__global__ void __launch_bounds__(256, 2) gnn_fused_kernel(
    const float* __restrict__ adj, const float* __restrict__ vec,
    const float* __restrict__ w1_rel, const float* __restrict__ w1_root,
    const float* __restrict__ b1,
    const float* __restrict__ w2_rel, const float* __restrict__ w2_root,
    const float* __restrict__ b2,
    const float* __restrict__ wf, const float* __restrict__ bf,
    float* __restrict__ out)
{
    extern __shared__ char smem[];
    __half* Vh    = (__half*)(smem + OFF_VH);
    __half* Wr    = (__half*)(smem + OFF_WR);
    float*  Wroot = (float*)(smem + OFF_WROOT);
    __half* H     = (__half*)(smem + OFF_H);
    float*  B1s   = (float*)(smem + OFF_B1);
    int*    JL    = (int*)(smem + OFF_JL);
    float*  VL    = (float*)(smem + OFF_VL);
    int*    CNT   = (int*)(smem + OFF_CNT);
    float*  PART  = (float*)(smem + OFF_PART);
    float*  X0s   = (float*)(smem + OFF_X0);
    float*  SAs   = (float*)(smem + OFF_SA);
    float*  SBs   = (float*)(smem + OFF_SB);

    const int tid  = threadIdx.x;
    const int lane = tid & 31;
    const int wid  = tid >> 5;
    const int b    = blockIdx.x;

    const float* abf = adj + (size_t)b * (NN * NN);
    const float* vcf = vec + (size_t)b * (NN * FF);

    // ---------------- Phase A: stage Vh (fp16), Wr (fp16), Wroot (fp32) -------
    {
        const float4* v4 = (const float4*)vcf;
        for (int p = tid; p < (NN * FF) / 4; p += 256) {
            float4 x = v4[p];
            float comp[4] = {x.x, x.y, x.z, x.w};
            int idx = p * 4;
#pragma unroll
            for (int q = 0; q < 4; ++q) {
                int ii = idx + q;
                int r = ii / FF, c = ii - r * FF;
                Vh[r * 72 + c] = __float2half(comp[q]);
            }
        }
        if (tid < NN) Vh[tid * 72 + 63] = __float2half(0.0f);  // zero pad col 63

        for (int idx = tid; idx < FF * DD; idx += 256) {
            int k = idx >> 6, n = idx & 63;
            Wr[k * 72 + n]     = __float2half(w1_rel[idx]);
            Wroot[k * 64 + n]  = w1_root[idx];
        }
        if (tid < 64) Wr[63 * 72 + tid] = __float2half(0.0f);  // pad k=63
        if (tid < 64) B1s[tid] = b1[tid];

        // warp 7: build needed-row list from adj row 0 (global, coalesced)
        if (wid == 7) {
            int base = 0;
#pragma unroll
            for (int e = 0; e < 8; ++e) {
                float v = abf[e * 32 + lane];
                unsigned m = __ballot_sync(0xffffffffu, v != 0.0f);
                if (v != 0.0f) {
                    int pos = base + __popc(m & ((1u << lane) - 1));
                    if (pos < 128) { JL[pos] = e * 32 + lane; VL[pos] = v; }
                }
                base += __popc(m);
            }
            if (lane == 0) *CNT = (base < 128) ? base : 128;
        }
    }
    __syncthreads();

    const int row16 = lane & 15;
    const int half8 = (lane >> 4) << 3;  // 0 or 8
    const int mb = wid * 32;             // 8 warps x 32 rows

    // ------- Projection: Hrel = Vh @ w1_rel (fp16 out), 8 warps x 32 rows ------
    {
        float acc[2][8][4];
#pragma unroll
        for (int mt = 0; mt < 2; ++mt)
#pragma unroll
            for (int q = 0; q < 8; ++q)
#pragma unroll
                for (int t = 0; t < 4; ++t) acc[mt][q][t] = 0.0f;

#pragma unroll
        for (int kt = 0; kt < 4; ++kt) {
            uint32_t a0[2][4];
#pragma unroll
            for (int mt = 0; mt < 2; ++mt)
                ldsm_x4(smem_u32(&Vh[(mb + mt * 16 + row16) * 72 + kt * 16 + half8]),
                        a0[mt][0], a0[mt][1], a0[mt][2], a0[mt][3]);
#pragma unroll
            for (int nt = 0; nt < 4; ++nt) {
                uint32_t b0, b1r, b2r, b3r;
                ldsm_x4t(smem_u32(&Wr[(kt * 16 + row16) * 72 + nt * 16 + half8]),
                         b0, b1r, b2r, b3r);
#pragma unroll
                for (int mt = 0; mt < 2; ++mt) {
                    mma16816(acc[mt][2 * nt],     a0[mt][0], a0[mt][1],
                             a0[mt][2], a0[mt][3], b0, b1r);
                    mma16816(acc[mt][2 * nt + 1], a0[mt][0], a0[mt][1],
                             a0[mt][2], a0[mt][3], b2r, b3r);
                }
            }
        }
        // epilogue: store Hrel fp16
        const int rloc = lane >> 2;
        const int c0   = (lane & 3) * 2;
#pragma unroll
        for (int mt = 0; mt < 2; ++mt)
#pragma unroll
            for (int q = 0; q < 8; ++q) {
                const int c = q * 8 + c0;
                const int r = mb + mt * 16 + rloc;
                *(half2*)&H[r * 72 + c] = __halves2half2(
                    __float2half_rn(acc[mt][q][0]), __float2half_rn(acc[mt][q][1]));
                *(half2*)&H[(r + 8) * 72 + c] = __halves2half2(
                    __float2half_rn(acc[mt][q][2]), __float2half_rn(acc[mt][q][3]));
            }
    }
    __syncthreads();

    // ------- Gather: only needed rows; agg from fp16 Hrel, Hroot exact fp32 ----
    {
        const int cnt = *CNT;
        float* vbuf = (float*)(smem + OFF_VBUF) + wid * 64;
        float px = 0.0f, py = 0.0f;

        for (int slot = wid; slot < cnt; slot += 8) {
            const int   j   = JL[slot];
            const float a0v = VL[slot];

            // issue global loads: adj row j + vec row j (fp32, exact)
            const float4* rowp = (const float4*)(abf + (size_t)j * NN);
            float4 va = ldcs4(&rowp[lane]);
            float4 vb = ldcs4(&rowp[32 + lane]);
            float  v0 = vcf[j * FF + lane];
            float  v1 = (lane < 31) ? vcf[j * FF + 32 + lane] : 0.0f;

            vbuf[lane] = v0;
            if (lane < 31) vbuf[32 + lane] = v1;
            __syncwarp();

            // sparse aggregation over Hrel (fp16 -> fp32)
            float accx = 0.0f, accy = 0.0f;
            float vals[8] = {va.x, va.y, va.z, va.w, vb.x, vb.y, vb.z, vb.w};
#pragma unroll
            for (int e = 0; e < 8; ++e) {
                float v = vals[e];
                unsigned m = __ballot_sync(0xffffffffu, v != 0.0f);
                while (m) {
                    int l = __ffs(m) - 1;
                    m &= m - 1;
                    float vv = __shfl_sync(0xffffffffu, v, l);
                    int kk = (e < 4) ? (l * 4 + e) : (128 + l * 4 + (e - 4));
                    float2 h = __half22float2(*(const half2*)&H[kk * 72 + 2 * lane]);
                    accx = fmaf(vv, h.x, accx);
                    accy = fmaf(vv, h.y, accy);
                }
            }

            // Hroot[j] exact fp32: vec row j (vbuf) @ Wroot
            float s0 = 0.0f, s1 = 0.0f;
#pragma unroll 9
            for (int k = 0; k < FF; ++k) {
                float vv = vbuf[k];
                float2 w = *(const float2*)&Wroot[k * 64 + 2 * lane];
                s0 = fmaf(vv, w.x, s0);
                s1 = fmaf(vv, w.y, s1);
            }

            float xv0 = fmaxf(accx + s0 + B1s[2 * lane], 0.0f);
            float xv1 = fmaxf(accy + s1 + B1s[2 * lane + 1], 0.0f);
            px = fmaf(a0v, xv0, px);
            py = fmaf(a0v, xv1, py);
            if (j == 0) {
                X0s[2 * lane]     = xv0;
                X0s[2 * lane + 1] = xv1;
            }
            __syncwarp();   // vbuf reuse guard
        }
        PART[wid * 64 + 2 * lane]     = px;
        PART[wid * 64 + 2 * lane + 1] = py;
    }
    __syncthreads();

    // ---------------- Final head: layer 2 at node 0 + linear head --------------
    if (tid < 64) {
        float s = 0.0f;
#pragma unroll
        for (int w = 0; w < 8; ++w) s += PART[w * 64 + tid];
        SAs[tid] = s;   // SA = adj[0,:] @ x
    }
    __syncthreads();
    if (tid < 64) {
        float acc = b2[tid];
#pragma unroll 8
        for (int d = 0; d < 64; ++d)
            acc += SAs[d] * w2_rel[d * 64 + tid] + X0s[d] * w2_root[d * 64 + tid];
        float y = fmaxf(acc, 0.0f);
        SBs[tid] = y + X0s[tid];  // x0 + y0
    }
    __syncthreads();
    if (tid < 2) {
        float s = bf[tid];
#pragma unroll 16
        for (int d = 0; d < 64; ++d) s = fmaf(SBs[d], wf[d * 2 + tid], s);
        out[(size_t)b * 2 + tid] = s;
    }
}

extern "C" void kernel_launch(void* const* d_in, const int* in_sizes, int n_in,
                              void* d_out, int out_size) {
    const float* adj     = (const float*)d_in[0];
    const float* vec     = (const float*)d_in[1];
    const float* w1_rel  = (const float*)d_in[2];
    const float* w1_root = (const float*)d_in[3];
    const float* b1      = (const float*)d_in[4];
    const float* w2_rel  = (const float*)d_in[5];
    const float* w2_root = (const float*)d_in[6];
    const float* b2      = (const float*)d_in[7];
    const float* wf      = (const float*)d_in[8];
    const float* bf      = (const float*)d_in[9];
    float* out = (float*)d_out;

    cudaFuncSetAttribute(gnn_fused_kernel,
                         cudaFuncAttributeMaxDynamicSharedMemorySize, SMEM_BYTES);
    gnn_fused_kernel<<<NB, 256, SMEM_BYTES>>>(
        adj, vec, w1_rel, w1_root, b1, w2_rel, w2_root, b2, wf, bf, out);
}

// round 13
// speedup vs baseline: 2.0423x; 1.0720x over previous
#include <cuda_runtime.h>
#include <cstdint>

// Problem constants
#define NB 1024
#define NN 256
#define FF 63
#define DD 64

// smem byte offsets (6 CTAs resident per SM)
#define OFF_WREL  0        // float W[64][64] buffer (w1_rel 63x64, then w2_rel 64x64)
#define OFF_WROOT 16384    // float W[64][64] buffer (w1_root, then w2_root)
#define OFF_B1    32768    // float[64]
#define OFF_TBUF  33024    // float tbuf[4 warps][64]; reused as SA/SB after gather
#define OFF_VBUF  34048    // float vbuf[4 warps][64]
#define OFF_JL    35072    // int[128]
#define OFF_VL    35584    // float[128]
#define OFF_CNT   36096    // int
#define OFF_PART  36112    // float[4][64]
#define OFF_X0    37136    // float[64]
#define SMEM_BYTES 37392

#define OFF_SA    OFF_TBUF          // float[64], overlays dead tbuf
#define OFF_SB    (OFF_TBUF + 256)  // float[64]

__device__ __forceinline__ float4 ldcs4(const float4* p) {
    float4 v;
    asm volatile("ld.global.cs.v4.f32 {%0,%1,%2,%3}, [%4];"
                 : "=f"(v.x), "=f"(v.y), "=f"(v.z), "=f"(v.w) : "l"(p));
    return v;
}

__global__ void __launch_bounds__(128, 6) gnn_fused_kernel(
    const float* __restrict__ adj, const float* __restrict__ vec,
    const float* __restrict__ w1_rel, const float* __restrict__ w1_root,
    const float* __restrict__ b1,
    const float* __restrict__ w2_rel, const float* __restrict__ w2_root,
    const float* __restrict__ b2,
    const float* __restrict__ wf, const float* __restrict__ bf,
    float* __restrict__ out)
{
    extern __shared__ char smem[];
    float* Wrel  = (float*)(smem + OFF_WREL);
    float* Wroot = (float*)(smem + OFF_WROOT);
    float* B1s   = (float*)(smem + OFF_B1);
    int*   JL    = (int*)(smem + OFF_JL);
    float* VL    = (float*)(smem + OFF_VL);
    int*   CNT   = (int*)(smem + OFF_CNT);
    float* PART  = (float*)(smem + OFF_PART);
    float* X0s   = (float*)(smem + OFF_X0);
    float* SAs   = (float*)(smem + OFF_SA);
    float* SBs   = (float*)(smem + OFF_SB);

    const int tid  = threadIdx.x;
    const int lane = tid & 31;
    const int wid  = tid >> 5;
    const int b    = blockIdx.x;

    const float* abf = adj + (size_t)b * (NN * NN);
    const float* vcf = vec + (size_t)b * (NN * FF);

    // ---------------- Phase A: stage w1 (fp32) + b1; warp 3 builds row-0 list --
    {
        const float4* wr4 = (const float4*)w1_rel;
        const float4* wo4 = (const float4*)w1_root;
        for (int p = tid; p < (FF * DD) / 4; p += 128) {
            ((float4*)Wrel)[p]  = wr4[p];
            ((float4*)Wroot)[p] = wo4[p];
        }
        if (tid < 64) B1s[tid] = b1[tid];

        if (wid == 3) {  // needed-row list from adj row 0
            int base = 0;
#pragma unroll
            for (int e = 0; e < 8; ++e) {
                float v = abf[e * 32 + lane];
                unsigned m = __ballot_sync(0xffffffffu, v != 0.0f);
                if (v != 0.0f) {
                    int pos = base + __popc(m & ((1u << lane) - 1));
                    if (pos < 128) { JL[pos] = e * 32 + lane; VL[pos] = v; }
                }
                base += __popc(m);
            }
            if (lane == 0) *CNT = (base < 128) ? base : 128;
        }
    }
    __syncthreads();

    // ---------------- Gather: warp-per-needed-row, all exact fp32 --------------
    {
        const int cnt = *CNT;
        float* tbuf = (float*)(smem + OFF_TBUF) + wid * 64;
        float* vbuf = (float*)(smem + OFF_VBUF) + wid * 64;
        float px = 0.0f, py = 0.0f;

        for (int slot = wid; slot < cnt; slot += 4) {
            const int   j   = JL[slot];
            const float a0v = VL[slot];

            // adj row j (read-once) + vec row j (for the root term)
            const float4* rowp = (const float4*)(abf + (size_t)j * NN);
            float4 va = ldcs4(&rowp[lane]);
            float4 vb = ldcs4(&rowp[32 + lane]);
            float vj0 = vcf[j * FF + lane];
            float vj1 = (lane < 31) ? vcf[j * FF + 32 + lane] : 0.0f;

            // t = sum_k adj[j,k] * vec[k]  (exact fp32, ~14 terms)
            float t0 = 0.0f, t1 = 0.0f;
            float vals[8] = {va.x, va.y, va.z, va.w, vb.x, vb.y, vb.z, vb.w};
#pragma unroll
            for (int e = 0; e < 8; ++e) {
                float v = vals[e];
                unsigned m = __ballot_sync(0xffffffffu, v != 0.0f);
                while (m) {
                    int l = __ffs(m) - 1;
                    m &= m - 1;
                    float vv = __shfl_sync(0xffffffffu, v, l);
                    int k = (e < 4) ? (l * 4 + e) : (128 + l * 4 + (e - 4));
                    t0 = fmaf(vv, vcf[k * FF + lane], t0);
                    if (lane < 31)
                        t1 = fmaf(vv, vcf[k * FF + 32 + lane], t1);
                }
            }
            tbuf[lane] = t0;
            vbuf[lane] = vj0;
            if (lane < 31) { tbuf[32 + lane] = t1; vbuf[32 + lane] = vj1; }
            __syncwarp();

            // x[j][c] = relu(t @ Wrel + vec[j] @ Wroot + b1), lane -> cols 2l,2l+1
            float a0 = B1s[2 * lane], a1 = B1s[2 * lane + 1];
#pragma unroll 9
            for (int k = 0; k < FF; ++k) {
                float tk = tbuf[k], vk = vbuf[k];
                float2 wr = *(const float2*)&Wrel[k * 64 + 2 * lane];
                float2 wo = *(const float2*)&Wroot[k * 64 + 2 * lane];
                a0 = fmaf(tk, wr.x, fmaf(vk, wo.x, a0));
                a1 = fmaf(tk, wr.y, fmaf(vk, wo.y, a1));
            }
            float xv0 = fmaxf(a0, 0.0f);
            float xv1 = fmaxf(a1, 0.0f);
            px = fmaf(a0v, xv0, px);
            py = fmaf(a0v, xv1, py);
            if (j == 0) {
                X0s[2 * lane]     = xv0;
                X0s[2 * lane + 1] = xv1;
            }
            __syncwarp();   // tbuf/vbuf reuse guard
        }
        PART[wid * 64 + 2 * lane]     = px;
        PART[wid * 64 + 2 * lane + 1] = py;
    }
    __syncthreads();

    // ------ Head: stage w2 into the (now correctly sized) weight buffers -------
    {
        const float4* w2r4 = (const float4*)w2_rel;
        const float4* w2o4 = (const float4*)w2_root;
        for (int p = tid; p < (DD * DD) / 4; p += 128) {
            ((float4*)Wrel)[p]  = w2r4[p];
            ((float4*)Wroot)[p] = w2o4[p];
        }
        if (tid < 64) {
            float s = PART[tid] + PART[64 + tid] + PART[128 + tid] +
                      PART[192 + tid];
            SAs[tid] = s;   // SA = adj[0,:] @ x   (SAs overlays dead tbuf)
        }
    }
    __syncthreads();
    if (tid < 64) {
        float acc = b2[tid];
#pragma unroll 8
        for (int d = 0; d < 64; ++d)
            acc = fmaf(SAs[d], Wrel[d * 64 + tid],
                       fmaf(X0s[d], Wroot[d * 64 + tid], acc));
        float y = fmaxf(acc, 0.0f);
        SBs[tid] = y + X0s[tid];  // x0 + y0
    }
    __syncthreads();
    if (tid < 2) {
        float s = bf[tid];
#pragma unroll 16
        for (int d = 0; d < 64; ++d) s = fmaf(SBs[d], wf[d * 2 + tid], s);
        out[(size_t)b * 2 + tid] = s;
    }
}

extern "C" void kernel_launch(void* const* d_in, const int* in_sizes, int n_in,
                              void* d_out, int out_size) {
    const float* adj     = (const float*)d_in[0];
    const float* vec     = (const float*)d_in[1];
    const float* w1_rel  = (const float*)d_in[2];
    const float* w1_root = (const float*)d_in[3];
    const float* b1      = (const float*)d_in[4];
    const float* w2_rel  = (const float*)d_in[5];
    const float* w2_root = (const float*)d_in[6];
    const float* b2      = (const float*)d_in[7];
    const float* wf      = (const float*)d_in[8];
    const float* bf      = (const float*)d_in[9];
    float* out = (float*)d_out;

    cudaFuncSetAttribute(gnn_fused_kernel,
                         cudaFuncAttributeMaxDynamicSharedMemorySize, SMEM_BYTES);
    gnn_fused_kernel<<<NB, 128, SMEM_BYTES>>>(
        adj, vec, w1_rel, w1_root, b1, w2_rel, w2_root, b2, wf, bf, out);
}

// round 14
// speedup vs baseline: 2.7939x; 1.3680x over previous
#include <cuda_runtime.h>
#include <cstdint>

// Problem constants
#define NB 1024
#define NN 256
#define FF 63
#define DD 64

// smem byte offsets (6 CTAs resident per SM)
#define OFF_WREL  0        // float W[64][64] buffer (w1_rel 63x64, then w2_rel 64x64)
#define OFF_WROOT 16384    // float W[64][64] buffer (w1_root, then w2_root)
#define OFF_B1    32768    // float[64]
#define OFF_TBUF  33024    // float tbuf[4 warps][64]; overlays KL (gather) and SA/SB (head)
#define OFF_VBUF  34048    // float vbuf[4 warps][64]; overlays KV (gather)
#define OFF_JL    35072    // int[128]
#define OFF_VL    35584    // float[128]
#define OFF_CNT   36096    // int
#define OFF_PART  36112    // float[4][64]
#define OFF_X0    37136    // float[64]
#define SMEM_BYTES 37392

#define OFF_SA    OFF_TBUF          // float[64], overlays dead tbuf in head
#define OFF_SB    (OFF_TBUF + 256)  // float[64]

__device__ __forceinline__ float4 ldcs4(const float4* p) {
    float4 v;
    asm volatile("ld.global.cs.v4.f32 {%0,%1,%2,%3}, [%4];"
                 : "=f"(v.x), "=f"(v.y), "=f"(v.z), "=f"(v.w) : "l"(p));
    return v;
}

__global__ void __launch_bounds__(128, 6) gnn_fused_kernel(
    const float* __restrict__ adj, const float* __restrict__ vec,
    const float* __restrict__ w1_rel, const float* __restrict__ w1_root,
    const float* __restrict__ b1,
    const float* __restrict__ w2_rel, const float* __restrict__ w2_root,
    const float* __restrict__ b2,
    const float* __restrict__ wf, const float* __restrict__ bf,
    float* __restrict__ out)
{
    extern __shared__ char smem[];
    float* Wrel  = (float*)(smem + OFF_WREL);
    float* Wroot = (float*)(smem + OFF_WROOT);
    float* B1s   = (float*)(smem + OFF_B1);
    int*   JL    = (int*)(smem + OFF_JL);
    float* VL    = (float*)(smem + OFF_VL);
    int*   CNT   = (int*)(smem + OFF_CNT);
    float* PART  = (float*)(smem + OFF_PART);
    float* X0s   = (float*)(smem + OFF_X0);
    float* SAs   = (float*)(smem + OFF_SA);
    float* SBs   = (float*)(smem + OFF_SB);

    const int tid  = threadIdx.x;
    const int lane = tid & 31;
    const int wid  = tid >> 5;
    const int b    = blockIdx.x;
    const unsigned ltmask = (1u << lane) - 1;

    const float* abf = adj + (size_t)b * (NN * NN);
    const float* vcf = vec + (size_t)b * (NN * FF);

    // ---------------- Phase A ------------------------------------------------
    // warp 3: issue adj row-0 loads FIRST (latency overlaps weight staging)
    float4 r0a, r0b;
    if (wid == 3) {
        const float4* rowp0 = (const float4*)abf;
        r0a = ldcs4(&rowp0[lane]);
        r0b = ldcs4(&rowp0[32 + lane]);
    }
    {
        const float4* wr4 = (const float4*)w1_rel;
        const float4* wo4 = (const float4*)w1_root;
        for (int p = tid; p < (FF * DD) / 4; p += 128) {
            ((float4*)Wrel)[p]  = wr4[p];
            ((float4*)Wroot)[p] = wo4[p];
        }
        if (tid < 64) B1s[tid] = b1[tid];
    }
    if (wid == 3) {  // needed-row list from adj row 0 (values now in regs)
        float vals[8] = {r0a.x, r0a.y, r0a.z, r0a.w, r0b.x, r0b.y, r0b.z, r0b.w};
        int base = 0;
#pragma unroll
        for (int e = 0; e < 8; ++e) {
            float v = vals[e];
            unsigned m = __ballot_sync(0xffffffffu, v != 0.0f);
            if (v != 0.0f) {
                int pos = base + __popc(m & ltmask);
                int k = (e < 4) ? (4 * lane + e) : (128 + 4 * lane + (e - 4));
                if (pos < 128) { JL[pos] = k; VL[pos] = v; }
            }
            base += __popc(m);
        }
        if (lane == 0) *CNT = (base < 128) ? base : 128;
    }
    __syncthreads();

    // ---------------- Gather: warp-per-needed-row, exact fp32, MLP-friendly ----
    {
        const int cnt = *CNT;
        float* tbuf = (float*)(smem + OFF_TBUF) + wid * 64;
        float* vbuf = (float*)(smem + OFF_VBUF) + wid * 64;
        int*   KL   = (int*)tbuf;    // overlay: (k) list during accumulate
        float* KV   = vbuf;          // overlay: (v) list during accumulate
        float px = 0.0f, py = 0.0f;

        int slot = wid;
        float4 va, vb;
        float vj0 = 0.0f, vj1 = 0.0f;
        if (slot < cnt) {
            const int j = JL[slot];
            const float4* rowp = (const float4*)(abf + (size_t)j * NN);
            va = ldcs4(&rowp[lane]);
            vb = ldcs4(&rowp[32 + lane]);
            vj0 = vcf[j * FF + lane];
            vj1 = (lane < 31) ? vcf[j * FF + 32 + lane] : 0.0f;
        }

        while (slot < cnt) {
            const int   j   = JL[slot];
            const float a0v = VL[slot];
            const int nslot = slot + 4;

            // prefetch next slot's adj row + vec row (hide 577-cyc latency)
            float4 nva, nvb;
            float nvj0 = 0.0f, nvj1 = 0.0f;
            if (nslot < cnt) {
                const int nj = JL[nslot];
                const float4* nrp = (const float4*)(abf + (size_t)nj * NN);
                nva = ldcs4(&nrp[lane]);
                nvb = ldcs4(&nrp[32 + lane]);
                nvj0 = vcf[nj * FF + lane];
                nvj1 = (lane < 31) ? vcf[nj * FF + 32 + lane] : 0.0f;
            }

            // pass 1: build (k,v) nonzero list in smem (pure ALU/ballot)
            float vals[8] = {va.x, va.y, va.z, va.w, vb.x, vb.y, vb.z, vb.w};
            int nk = 0;
#pragma unroll
            for (int e = 0; e < 8; ++e) {
                float v = vals[e];
                unsigned m = __ballot_sync(0xffffffffu, v != 0.0f);
                if (v != 0.0f) {
                    int pos = nk + __popc(m & ltmask);
                    int k = (e < 4) ? (4 * lane + e) : (128 + 4 * lane + (e - 4));
                    if (pos < 64) { KL[pos] = k; KV[pos] = v; }
                }
                nk += __popc(m);
            }
            if (nk > 64) nk = 64;
            __syncwarp();

            // pass 2: accumulate t = sum_k v_k * vec[k] with 2-wide ILP
            float t0a = 0.0f, t1a = 0.0f, t0b = 0.0f, t1b = 0.0f;
            int i = 0;
#pragma unroll 2
            for (; i + 2 <= nk; i += 2) {
                int   k0 = KL[i],     k1 = KL[i + 1];
                float w0 = KV[i],     w1 = KV[i + 1];
                const float* r0 = vcf + k0 * FF;
                const float* r1 = vcf + k1 * FF;
                float a00 = r0[lane];
                float a10 = r1[lane];
                float a01 = 0.0f, a11 = 0.0f;
                if (lane < 31) { a01 = r0[32 + lane]; a11 = r1[32 + lane]; }
                t0a = fmaf(w0, a00, t0a);
                t0b = fmaf(w1, a10, t0b);
                t1a = fmaf(w0, a01, t1a);
                t1b = fmaf(w1, a11, t1b);
            }
            if (i < nk) {
                int   k0 = KL[i];
                float w0 = KV[i];
                const float* r0 = vcf + k0 * FF;
                t0a = fmaf(w0, r0[lane], t0a);
                if (lane < 31) t1a = fmaf(w0, r0[32 + lane], t1a);
            }
            float t0 = t0a + t0b, t1 = t1a + t1b;
            __syncwarp();   // KL/KV dead; tbuf/vbuf reuse below

            tbuf[lane] = t0;
            vbuf[lane] = vj0;
            if (lane < 31) { tbuf[32 + lane] = t1; vbuf[32 + lane] = vj1; }
            __syncwarp();

            // x[j][c] = relu(t @ Wrel + vec[j] @ Wroot + b1), lane -> cols 2l,2l+1
            float a0 = B1s[2 * lane], a1 = B1s[2 * lane + 1];
#pragma unroll 9
            for (int k = 0; k < FF; ++k) {
                float tk = tbuf[k], vk = vbuf[k];
                float2 wr = *(const float2*)&Wrel[k * 64 + 2 * lane];
                float2 wo = *(const float2*)&Wroot[k * 64 + 2 * lane];
                a0 = fmaf(tk, wr.x, fmaf(vk, wo.x, a0));
                a1 = fmaf(tk, wr.y, fmaf(vk, wo.y, a1));
            }
            float xv0 = fmaxf(a0, 0.0f);
            float xv1 = fmaxf(a1, 0.0f);
            px = fmaf(a0v, xv0, px);
            py = fmaf(a0v, xv1, py);
            if (j == 0) {
                X0s[2 * lane]     = xv0;
                X0s[2 * lane + 1] = xv1;
            }
            __syncwarp();   // tbuf/vbuf reuse guard

            va = nva; vb = nvb; vj0 = nvj0; vj1 = nvj1;
            slot = nslot;
        }
        PART[wid * 64 + 2 * lane]     = px;
        PART[wid * 64 + 2 * lane + 1] = py;
    }
    __syncthreads();

    // ------ Head: stage w2 into the weight buffers, then layer 2 ---------------
    {
        const float4* w2r4 = (const float4*)w2_rel;
        const float4* w2o4 = (const float4*)w2_root;
        for (int p = tid; p < (DD * DD) / 4; p += 128) {
            ((float4*)Wrel)[p]  = w2r4[p];
            ((float4*)Wroot)[p] = w2o4[p];
        }
        if (tid < 64) {
            float s = PART[tid] + PART[64 + tid] + PART[128 + tid] +
                      PART[192 + tid];
            SAs[tid] = s;   // SA = adj[0,:] @ x
        }
    }
    __syncthreads();
    if (tid < 64) {
        float acc = b2[tid];
#pragma unroll 8
        for (int d = 0; d < 64; ++d)
            acc = fmaf(SAs[d], Wrel[d * 64 + tid],
                       fmaf(X0s[d], Wroot[d * 64 + tid], acc));
        float y = fmaxf(acc, 0.0f);
        SBs[tid] = y + X0s[tid];  // x0 + y0
    }
    __syncthreads();
    if (tid < 2) {
        float s = bf[tid];
#pragma unroll 16
        for (int d = 0; d < 64; ++d) s = fmaf(SBs[d], wf[d * 2 + tid], s);
        out[(size_t)b * 2 + tid] = s;
    }
}

extern "C" void kernel_launch(void* const* d_in, const int* in_sizes, int n_in,
                              void* d_out, int out_size) {
    const float* adj     = (const float*)d_in[0];
    const float* vec     = (const float*)d_in[1];
    const float* w1_rel  = (const float*)d_in[2];
    const float* w1_root = (const float*)d_in[3];
    const float* b1      = (const float*)d_in[4];
    const float* w2_rel  = (const float*)d_in[5];
    const float* w2_root = (const float*)d_in[6];
    const float* b2      = (const float*)d_in[7];
    const float* wf      = (const float*)d_in[8];
    const float* bf      = (const float*)d_in[9];
    float* out = (float*)d_out;

    cudaFuncSetAttribute(gnn_fused_kernel,
                         cudaFuncAttributeMaxDynamicSharedMemorySize, SMEM_BYTES);
    gnn_fused_kernel<<<NB, 128, SMEM_BYTES>>>(
        adj, vec, w1_rel, w1_root, b1, w2_rel, w2_root, b2, wf, bf, out);
}

// round 15
// speedup vs baseline: 2.9809x; 1.0669x over previous
#include <cuda_runtime.h>
#include <cstdint>

// Problem constants
#define NB 1024
#define NN 256
#define FF 63
#define DD 64

// smem byte offsets (target 5-6 CTAs resident per SM)
#define OFF_WREL  0        // float W[64][64] buffer (w1_rel 63x64 + zero row, then w2_rel)
#define OFF_WROOT 16384    // float W[64][64] buffer (w1_root + zero row, then w2_root)
#define OFF_B1    32768    // float[64]
#define OFF_TBUF  33024    // float tbuf[4 warps][64]; overlays KL (gather) and SA/SB (head)
#define OFF_VBUF  34048    // float vbuf[4 warps][64]; overlays KV (gather)
#define OFF_JL    35072    // int[128]
#define OFF_VL    35584    // float[128]
#define OFF_CNT   36096    // int
#define OFF_PART  36112    // float[4][64]
#define OFF_X0    37136    // float[64]
#define SMEM_BYTES 37392

#define OFF_SA    OFF_TBUF          // float[64], overlays dead tbuf in head
#define OFF_SB    (OFF_TBUF + 256)  // float[64]

__device__ __forceinline__ float4 ldcs4(const float4* p) {
    float4 v;
    asm volatile("ld.global.cs.v4.f32 {%0,%1,%2,%3}, [%4];"
                 : "=f"(v.x), "=f"(v.y), "=f"(v.z), "=f"(v.w) : "l"(p));
    return v;
}

__global__ void __launch_bounds__(128, 5) gnn_fused_kernel(
    const float* __restrict__ adj, const float* __restrict__ vec,
    const float* __restrict__ w1_rel, const float* __restrict__ w1_root,
    const float* __restrict__ b1,
    const float* __restrict__ w2_rel, const float* __restrict__ w2_root,
    const float* __restrict__ b2,
    const float* __restrict__ wf, const float* __restrict__ bf,
    float* __restrict__ out)
{
    extern __shared__ char smem[];
    float* Wrel  = (float*)(smem + OFF_WREL);
    float* Wroot = (float*)(smem + OFF_WROOT);
    float* B1s   = (float*)(smem + OFF_B1);
    int*   JL    = (int*)(smem + OFF_JL);
    float* VL    = (float*)(smem + OFF_VL);
    int*   CNT   = (int*)(smem + OFF_CNT);
    float* PART  = (float*)(smem + OFF_PART);
    float* X0s   = (float*)(smem + OFF_X0);
    float* SAs   = (float*)(smem + OFF_SA);
    float* SBs   = (float*)(smem + OFF_SB);

    const int tid  = threadIdx.x;
    const int lane = tid & 31;
    const int wid  = tid >> 5;
    const int b    = blockIdx.x;
    const unsigned ltmask = (1u << lane) - 1;

    const float* abf = adj + (size_t)b * (NN * NN);
    const float* vcf = vec + (size_t)b * (NN * FF);

    // ---------------- Phase A ------------------------------------------------
    // warp 3: issue adj row-0 loads FIRST (latency overlaps weight staging)
    float4 r0a, r0b;
    if (wid == 3) {
        const float4* rowp0 = (const float4*)abf;
        r0a = ldcs4(&rowp0[lane]);
        r0b = ldcs4(&rowp0[32 + lane]);
    }
    {
        const float4* wr4 = (const float4*)w1_rel;
        const float4* wo4 = (const float4*)w1_root;
        for (int p = tid; p < (FF * DD) / 4; p += 128) {
            ((float4*)Wrel)[p]  = wr4[p];
            ((float4*)Wroot)[p] = wo4[p];
        }
        // zero-pad k=63 row of both weight buffers (enables even 64-iter matvec)
        if (tid < 64) Wrel[63 * 64 + tid] = 0.0f;
        else          Wroot[63 * 64 + (tid - 64)] = 0.0f;
        if (tid < 64) B1s[tid] = b1[tid];
    }
    if (wid == 3) {  // needed-row list from adj row 0 (values now in regs)
        float vals[8] = {r0a.x, r0a.y, r0a.z, r0a.w, r0b.x, r0b.y, r0b.z, r0b.w};
        int base = 0;
#pragma unroll
        for (int e = 0; e < 8; ++e) {
            float v = vals[e];
            unsigned m = __ballot_sync(0xffffffffu, v != 0.0f);
            if (v != 0.0f) {
                int pos = base + __popc(m & ltmask);
                int k = (e < 4) ? (4 * lane + e) : (128 + 4 * lane + (e - 4));
                if (pos < 128) { JL[pos] = k; VL[pos] = v; }
            }
            base += __popc(m);
        }
        if (lane == 0) *CNT = (base < 128) ? base : 128;
    }
    __syncthreads();

    // ---------------- Gather: warp-per-needed-row, exact fp32 ------------------
    {
        const int cnt = *CNT;
        float* tbuf = (float*)(smem + OFF_TBUF) + wid * 64;
        float* vbuf = (float*)(smem + OFF_VBUF) + wid * 64;
        int*   KL   = (int*)tbuf;    // overlay: (k) list during accumulate
        float* KV   = vbuf;          // overlay: (v) list during accumulate
        float px = 0.0f, py = 0.0f;

        int slot = wid;
        float4 va, vb;
        float vj0 = 0.0f, vj1 = 0.0f;
        if (slot < cnt) {
            const int j = JL[slot];
            const float4* rowp = (const float4*)(abf + (size_t)j * NN);
            va = ldcs4(&rowp[lane]);
            vb = ldcs4(&rowp[32 + lane]);
            vj0 = vcf[j * FF + lane];
            vj1 = (lane < 31) ? vcf[j * FF + 32 + lane] : 0.0f;
        }

        while (slot < cnt) {
            const int   j   = JL[slot];
            const float a0v = VL[slot];
            const int nslot = slot + 4;

            // prefetch next slot's adj row + vec row (hide latency)
            float4 nva, nvb;
            float nvj0 = 0.0f, nvj1 = 0.0f;
            if (nslot < cnt) {
                const int nj = JL[nslot];
                const float4* nrp = (const float4*)(abf + (size_t)nj * NN);
                nva = ldcs4(&nrp[lane]);
                nvb = ldcs4(&nrp[32 + lane]);
                nvj0 = vcf[nj * FF + lane];
                nvj1 = (lane < 31) ? vcf[nj * FF + 32 + lane] : 0.0f;
            }

            // pass 1: build (k,v) nonzero list in smem (pure ALU/ballot)
            float vals[8] = {va.x, va.y, va.z, va.w, vb.x, vb.y, vb.z, vb.w};
            int nk = 0;
#pragma unroll
            for (int e = 0; e < 8; ++e) {
                float v = vals[e];
                unsigned m = __ballot_sync(0xffffffffu, v != 0.0f);
                if (v != 0.0f) {
                    int pos = nk + __popc(m & ltmask);
                    int k = (e < 4) ? (4 * lane + e) : (128 + 4 * lane + (e - 4));
                    if (pos < 64) { KL[pos] = k; KV[pos] = v; }
                }
                nk += __popc(m);
            }
            if (nk > 64) nk = 64;
            __syncwarp();

            // pass 2: accumulate t = sum_k v_k * vec[k], 4-wide (8 LDGs in flight)
            float t0c[4] = {0, 0, 0, 0}, t1c[4] = {0, 0, 0, 0};
            int i = 0;
            for (; i + 4 <= nk; i += 4) {
                int   k0 = KL[i],     k1 = KL[i + 1];
                int   k2 = KL[i + 2], k3 = KL[i + 3];
                float w0 = KV[i],     w1 = KV[i + 1];
                float w2 = KV[i + 2], w3 = KV[i + 3];
                const float* r0 = vcf + k0 * FF;
                const float* r1 = vcf + k1 * FF;
                const float* r2 = vcf + k2 * FF;
                const float* r3 = vcf + k3 * FF;
                float a00 = r0[lane], a10 = r1[lane];
                float a20 = r2[lane], a30 = r3[lane];
                float a01 = 0, a11 = 0, a21 = 0, a31 = 0;
                if (lane < 31) {
                    a01 = r0[32 + lane]; a11 = r1[32 + lane];
                    a21 = r2[32 + lane]; a31 = r3[32 + lane];
                }
                t0c[0] = fmaf(w0, a00, t0c[0]);
                t0c[1] = fmaf(w1, a10, t0c[1]);
                t0c[2] = fmaf(w2, a20, t0c[2]);
                t0c[3] = fmaf(w3, a30, t0c[3]);
                t1c[0] = fmaf(w0, a01, t1c[0]);
                t1c[1] = fmaf(w1, a11, t1c[1]);
                t1c[2] = fmaf(w2, a21, t1c[2]);
                t1c[3] = fmaf(w3, a31, t1c[3]);
            }
            for (; i < nk; ++i) {
                int   k0 = KL[i];
                float w0 = KV[i];
                const float* r0 = vcf + k0 * FF;
                t0c[0] = fmaf(w0, r0[lane], t0c[0]);
                if (lane < 31) t1c[0] = fmaf(w0, r0[32 + lane], t1c[0]);
            }
            float t0 = (t0c[0] + t0c[1]) + (t0c[2] + t0c[3]);
            float t1 = (t1c[0] + t1c[1]) + (t1c[2] + t1c[3]);
            __syncwarp();   // KL/KV dead; tbuf/vbuf reuse below

            tbuf[lane] = t0;
            vbuf[lane] = vj0;
            if (lane < 31) { tbuf[32 + lane] = t1; vbuf[32 + lane] = t1 * 0.0f + vj1; }
            if (lane == 31) { tbuf[63] = 0.0f; vbuf[63] = 0.0f; }  // pad k=63
            __syncwarp();

            // x[j][c] = relu(t @ Wrel + vec[j] @ Wroot + b1), 8 independent chains
            float cT0e = 0, cT0o = 0, cV0e = 0, cV0o = 0;
            float cT1e = 0, cT1o = 0, cV1e = 0, cV1o = 0;
#pragma unroll 8
            for (int k = 0; k < 64; k += 2) {
                float tk0 = tbuf[k],     vk0 = vbuf[k];
                float tk1 = tbuf[k + 1], vk1 = vbuf[k + 1];
                float2 wr0 = *(const float2*)&Wrel[k * 64 + 2 * lane];
                float2 wo0 = *(const float2*)&Wroot[k * 64 + 2 * lane];
                float2 wr1 = *(const float2*)&Wrel[(k + 1) * 64 + 2 * lane];
                float2 wo1 = *(const float2*)&Wroot[(k + 1) * 64 + 2 * lane];
                cT0e = fmaf(tk0, wr0.x, cT0e);
                cT0o = fmaf(tk1, wr1.x, cT0o);
                cV0e = fmaf(vk0, wo0.x, cV0e);
                cV0o = fmaf(vk1, wo1.x, cV0o);
                cT1e = fmaf(tk0, wr0.y, cT1e);
                cT1o = fmaf(tk1, wr1.y, cT1o);
                cV1e = fmaf(vk0, wo0.y, cV1e);
                cV1o = fmaf(vk1, wo1.y, cV1o);
            }
            float xv0 = fmaxf(((cT0e + cT0o) + (cV0e + cV0o)) + B1s[2 * lane], 0.0f);
            float xv1 = fmaxf(((cT1e + cT1o) + (cV1e + cV1o)) + B1s[2 * lane + 1],
                              0.0f);
            px = fmaf(a0v, xv0, px);
            py = fmaf(a0v, xv1, py);
            if (j == 0) {
                X0s[2 * lane]     = xv0;
                X0s[2 * lane + 1] = xv1;
            }
            __syncwarp();   // tbuf/vbuf reuse guard

            va = nva; vb = nvb; vj0 = nvj0; vj1 = nvj1;
            slot = nslot;
        }
        PART[wid * 64 + 2 * lane]     = px;
        PART[wid * 64 + 2 * lane + 1] = py;
    }
    __syncthreads();

    // ------ Head: stage w2 into the weight buffers, then layer 2 ---------------
    {
        const float4* w2r4 = (const float4*)w2_rel;
        const float4* w2o4 = (const float4*)w2_root;
        for (int p = tid; p < (DD * DD) / 4; p += 128) {
            ((float4*)Wrel)[p]  = w2r4[p];
            ((float4*)Wroot)[p] = w2o4[p];
        }
        if (tid < 64) {
            float s = PART[tid] + PART[64 + tid] + PART[128 + tid] +
                      PART[192 + tid];
            SAs[tid] = s;   // SA = adj[0,:] @ x
        }
    }
    __syncthreads();
    if (tid < 64) {
        float cA = b2[tid], cB = 0, cC = 0, cD = 0;
#pragma unroll 8
        for (int d = 0; d < 64; d += 2) {
            cA = fmaf(SAs[d],     Wrel[d * 64 + tid],        cA);
            cB = fmaf(X0s[d],     Wroot[d * 64 + tid],       cB);
            cC = fmaf(SAs[d + 1], Wrel[(d + 1) * 64 + tid],  cC);
            cD = fmaf(X0s[d + 1], Wroot[(d + 1) * 64 + tid], cD);
        }
        float y = fmaxf((cA + cC) + (cB + cD), 0.0f);
        SBs[tid] = y + X0s[tid];  // x0 + y0
    }
    __syncthreads();
    if (tid < 2) {
        float s = bf[tid];
#pragma unroll 16
        for (int d = 0; d < 64; ++d) s = fmaf(SBs[d], wf[d * 2 + tid], s);
        out[(size_t)b * 2 + tid] = s;
    }
}

extern "C" void kernel_launch(void* const* d_in, const int* in_sizes, int n_in,
                              void* d_out, int out_size) {
    const float* adj     = (const float*)d_in[0];
    const float* vec     = (const float*)d_in[1];
    const float* w1_rel  = (const float*)d_in[2];
    const float* w1_root = (const float*)d_in[3];
    const float* b1      = (const float*)d_in[4];
    const float* w2_rel  = (const float*)d_in[5];
    const float* w2_root = (const float*)d_in[6];
    const float* b2      = (const float*)d_in[7];
    const float* wf      = (const float*)d_in[8];
    const float* bf      = (const float*)d_in[9];
    float* out = (float*)d_out;

    cudaFuncSetAttribute(gnn_fused_kernel,
                         cudaFuncAttributeMaxDynamicSharedMemorySize, SMEM_BYTES);
    gnn_fused_kernel<<<NB, 128, SMEM_BYTES>>>(
        adj, vec, w1_rel, w1_root, b1, w2_rel, w2_root, b2, wf, bf, out);
}

// round 16
// speedup vs baseline: 3.2906x; 1.1039x over previous
#include <cuda_runtime.h>
#include <cstdint>

// Problem constants
#define NB 1024
#define NN 256
#define FF 63
#define DD 64

// 2 batches per CTA, 256 threads (8 warps), shared work queue
// smem byte offsets
#define OFF_WREL  0        // float W[64][64] (w1_rel + zero row; w2_rel in head)
#define OFF_WROOT 16384    // float W[64][64] (w1_root + zero row; w2_root in head)
#define OFF_B1    32768    // float[64]
#define OFF_TBUF  33024    // float tbuf[8 warps][64]; overlays KL; SA/SB in head
#define OFF_VBUF  35072    // float vbuf[8 warps][64]; overlays KV
#define OFF_JL    37120    // int[2][128] row indices per batch
#define OFF_VL    38144    // float[2][128] adj[0,j] values per batch
#define OFF_CNT   39168    // int[4]
#define OFF_PART  39184    // float[8 warps][2 batches][64]
#define OFF_X0    43280    // float[2][64]
#define SMEM_BYTES 43792

#define OFF_SA    OFF_TBUF          // float[128], overlays dead tbuf in head
#define OFF_SB    (OFF_TBUF + 512)  // float[128]

__device__ __forceinline__ float4 ldcs4(const float4* p) {
    float4 v;
    asm volatile("ld.global.cs.v4.f32 {%0,%1,%2,%3}, [%4];"
                 : "=f"(v.x), "=f"(v.y), "=f"(v.z), "=f"(v.w) : "l"(p));
    return v;
}

__global__ void __launch_bounds__(256, 4) gnn_fused_kernel(
    const float* __restrict__ adj, const float* __restrict__ vec,
    const float* __restrict__ w1_rel, const float* __restrict__ w1_root,
    const float* __restrict__ b1,
    const float* __restrict__ w2_rel, const float* __restrict__ w2_root,
    const float* __restrict__ b2,
    const float* __restrict__ wf, const float* __restrict__ bf,
    float* __restrict__ out)
{
    extern __shared__ char smem[];
    float* Wrel  = (float*)(smem + OFF_WREL);
    float* Wroot = (float*)(smem + OFF_WROOT);
    float* B1s   = (float*)(smem + OFF_B1);
    int*   JL    = (int*)(smem + OFF_JL);
    float* VL    = (float*)(smem + OFF_VL);
    int*   CNT   = (int*)(smem + OFF_CNT);
    float* PART  = (float*)(smem + OFF_PART);
    float* X0s   = (float*)(smem + OFF_X0);
    float* SAs   = (float*)(smem + OFF_SA);
    float* SBs   = (float*)(smem + OFF_SB);

    const int tid  = threadIdx.x;
    const int lane = tid & 31;
    const int wid  = tid >> 5;
    const unsigned ltmask = (1u << lane) - 1;

    const int b0 = blockIdx.x * 2;
    const float* abf[2] = {adj + (size_t)b0 * (NN * NN),
                           adj + (size_t)(b0 + 1) * (NN * NN)};
    const float* vcf[2] = {vec + (size_t)b0 * (NN * FF),
                           vec + (size_t)(b0 + 1) * (NN * FF)};

    // ---------------- Phase A ------------------------------------------------
    // warps 6/7: issue adj row-0 loads FIRST (latency overlaps weight staging)
    float4 r0a, r0b;
    if (wid >= 6) {
        const float4* rowp0 = (const float4*)abf[wid - 6];
        r0a = ldcs4(&rowp0[lane]);
        r0b = ldcs4(&rowp0[32 + lane]);
    }
    {
        const float4* wr4 = (const float4*)w1_rel;
        const float4* wo4 = (const float4*)w1_root;
        for (int p = tid; p < (FF * DD) / 4; p += 256) {
            ((float4*)Wrel)[p]  = wr4[p];
            ((float4*)Wroot)[p] = wo4[p];
        }
        // zero-pad k=63 row (enables even 64-iter matvec)
        if (tid < 64)       Wrel[63 * 64 + tid] = 0.0f;
        else if (tid < 128) Wroot[63 * 64 + (tid - 64)] = 0.0f;
        if (tid < 64) B1s[tid] = b1[tid];
    }
    if (wid >= 6) {  // build needed-row lists (values already in regs)
        const int bsel = wid - 6;
        float vals[8] = {r0a.x, r0a.y, r0a.z, r0a.w, r0b.x, r0b.y, r0b.z, r0b.w};
        int base = 0;
#pragma unroll
        for (int e = 0; e < 8; ++e) {
            float v = vals[e];
            unsigned m = __ballot_sync(0xffffffffu, v != 0.0f);
            if (v != 0.0f) {
                int pos = base + __popc(m & ltmask);
                int k = (e < 4) ? (4 * lane + e) : (128 + 4 * lane + (e - 4));
                if (pos < 128) {
                    JL[bsel * 128 + pos] = k;
                    VL[bsel * 128 + pos] = v;
                }
            }
            base += __popc(m);
        }
        if (lane == 0) CNT[bsel] = (base < 128) ? base : 128;
    }
    __syncthreads();

    // ---------------- Gather: shared queue over both batches -------------------
    {
        const int cntA  = CNT[0];
        const int total = cntA + CNT[1];
        float* tbuf = (float*)(smem + OFF_TBUF) + wid * 64;
        float* vbuf = (float*)(smem + OFF_VBUF) + wid * 64;
        int*   KL   = (int*)tbuf;    // overlay during accumulate
        float* KV   = vbuf;
        float px[2] = {0.0f, 0.0f}, py[2] = {0.0f, 0.0f};

        int slot = wid;
        int sj = 0, sb = 0;
        float sa0v = 0.0f;
        float4 va, vb;
        float vj0 = 0.0f, vj1 = 0.0f;
        if (slot < total) {
            sb = (slot < cntA) ? 0 : 1;
            const int qi = (sb == 0) ? slot : (128 + slot - cntA);
            sj = JL[qi]; sa0v = VL[qi];
            const float4* rowp = (const float4*)(abf[sb] + (size_t)sj * NN);
            va = ldcs4(&rowp[lane]);
            vb = ldcs4(&rowp[32 + lane]);
            vj0 = vcf[sb][sj * FF + lane];
            vj1 = (lane < 31) ? vcf[sb][sj * FF + 32 + lane] : 0.0f;
        }

        while (slot < total) {
            const int   j    = sj;
            const int   bsel = sb;
            const float a0v  = sa0v;
            const float* vcs = vcf[bsel];
            const int nslot  = slot + 8;

            // decode + prefetch next slot
            float4 nva, nvb;
            float nvj0 = 0.0f, nvj1 = 0.0f;
            int nj = 0, nb = 0;
            float na0v = 0.0f;
            if (nslot < total) {
                nb = (nslot < cntA) ? 0 : 1;
                const int qi = (nb == 0) ? nslot : (128 + nslot - cntA);
                nj = JL[qi]; na0v = VL[qi];
                const float4* nrp = (const float4*)(abf[nb] + (size_t)nj * NN);
                nva = ldcs4(&nrp[lane]);
                nvb = ldcs4(&nrp[32 + lane]);
                nvj0 = vcf[nb][nj * FF + lane];
                nvj1 = (lane < 31) ? vcf[nb][nj * FF + 32 + lane] : 0.0f;
            }

            // pass 1: build (k,v) nonzero list in smem (pure ALU/ballot)
            float vals[8] = {va.x, va.y, va.z, va.w, vb.x, vb.y, vb.z, vb.w};
            int nk = 0;
#pragma unroll
            for (int e = 0; e < 8; ++e) {
                float v = vals[e];
                unsigned m = __ballot_sync(0xffffffffu, v != 0.0f);
                if (v != 0.0f) {
                    int pos = nk + __popc(m & ltmask);
                    int k = (e < 4) ? (4 * lane + e) : (128 + 4 * lane + (e - 4));
                    if (pos < 64) { KL[pos] = k; KV[pos] = v; }
                }
                nk += __popc(m);
            }
            if (nk > 64) nk = 64;
            __syncwarp();

            // pass 2: t = sum_k v_k * vec[k], 4-wide (8 LDGs in flight)
            float t0c[4] = {0, 0, 0, 0}, t1c[4] = {0, 0, 0, 0};
            int i = 0;
            for (; i + 4 <= nk; i += 4) {
                int   k0 = KL[i],     k1 = KL[i + 1];
                int   k2 = KL[i + 2], k3 = KL[i + 3];
                float w0 = KV[i],     w1 = KV[i + 1];
                float w2 = KV[i + 2], w3 = KV[i + 3];
                const float* r0 = vcs + k0 * FF;
                const float* r1 = vcs + k1 * FF;
                const float* r2 = vcs + k2 * FF;
                const float* r3 = vcs + k3 * FF;
                float a00 = r0[lane], a10 = r1[lane];
                float a20 = r2[lane], a30 = r3[lane];
                float a01 = 0, a11 = 0, a21 = 0, a31 = 0;
                if (lane < 31) {
                    a01 = r0[32 + lane]; a11 = r1[32 + lane];
                    a21 = r2[32 + lane]; a31 = r3[32 + lane];
                }
                t0c[0] = fmaf(w0, a00, t0c[0]);
                t0c[1] = fmaf(w1, a10, t0c[1]);
                t0c[2] = fmaf(w2, a20, t0c[2]);
                t0c[3] = fmaf(w3, a30, t0c[3]);
                t1c[0] = fmaf(w0, a01, t1c[0]);
                t1c[1] = fmaf(w1, a11, t1c[1]);
                t1c[2] = fmaf(w2, a21, t1c[2]);
                t1c[3] = fmaf(w3, a31, t1c[3]);
            }
            for (; i < nk; ++i) {
                int   k0 = KL[i];
                float w0 = KV[i];
                const float* r0 = vcs + k0 * FF;
                t0c[0] = fmaf(w0, r0[lane], t0c[0]);
                if (lane < 31) t1c[0] = fmaf(w0, r0[32 + lane], t1c[0]);
            }
            float t0 = (t0c[0] + t0c[1]) + (t0c[2] + t0c[3]);
            float t1 = (t1c[0] + t1c[1]) + (t1c[2] + t1c[3]);
            __syncwarp();   // KL/KV dead; tbuf/vbuf reuse below

            tbuf[lane] = t0;
            vbuf[lane] = vj0;
            if (lane < 31) { tbuf[32 + lane] = t1; vbuf[32 + lane] = vj1; }
            if (lane == 31) { tbuf[63] = 0.0f; vbuf[63] = 0.0f; }  // pad k=63
            __syncwarp();

            // x[j][c] = relu(t @ Wrel + vec[j] @ Wroot + b1), 8 independent chains
            float cT0e = 0, cT0o = 0, cV0e = 0, cV0o = 0;
            float cT1e = 0, cT1o = 0, cV1e = 0, cV1o = 0;
#pragma unroll 8
            for (int k = 0; k < 64; k += 2) {
                float tk0 = tbuf[k],     vk0 = vbuf[k];
                float tk1 = tbuf[k + 1], vk1 = vbuf[k + 1];
                float2 wr0 = *(const float2*)&Wrel[k * 64 + 2 * lane];
                float2 wo0 = *(const float2*)&Wroot[k * 64 + 2 * lane];
                float2 wr1 = *(const float2*)&Wrel[(k + 1) * 64 + 2 * lane];
                float2 wo1 = *(const float2*)&Wroot[(k + 1) * 64 + 2 * lane];
                cT0e = fmaf(tk0, wr0.x, cT0e);
                cT0o = fmaf(tk1, wr1.x, cT0o);
                cV0e = fmaf(vk0, wo0.x, cV0e);
                cV0o = fmaf(vk1, wo1.x, cV0o);
                cT1e = fmaf(tk0, wr0.y, cT1e);
                cT1o = fmaf(tk1, wr1.y, cT1o);
                cV1e = fmaf(vk0, wo0.y, cV1e);
                cV1o = fmaf(vk1, wo1.y, cV1o);
            }
            float xv0 = fmaxf(((cT0e + cT0o) + (cV0e + cV0o)) + B1s[2 * lane], 0.0f);
            float xv1 = fmaxf(((cT1e + cT1o) + (cV1e + cV1o)) + B1s[2 * lane + 1],
                              0.0f);
            px[bsel] = fmaf(a0v, xv0, px[bsel]);
            py[bsel] = fmaf(a0v, xv1, py[bsel]);
            if (j == 0) {
                X0s[bsel * 64 + 2 * lane]     = xv0;
                X0s[bsel * 64 + 2 * lane + 1] = xv1;
            }
            __syncwarp();   // tbuf/vbuf reuse guard

            va = nva; vb = nvb; vj0 = nvj0; vj1 = nvj1;
            sj = nj; sb = nb; sa0v = na0v;
            slot = nslot;
        }
#pragma unroll
        for (int bs = 0; bs < 2; ++bs) {
            PART[(wid * 2 + bs) * 64 + 2 * lane]     = px[bs];
            PART[(wid * 2 + bs) * 64 + 2 * lane + 1] = py[bs];
        }
    }
    __syncthreads();

    // ------ Head: stage w2 into the weight buffers, then both batches' layer 2 -
    {
        const float4* w2r4 = (const float4*)w2_rel;
        const float4* w2o4 = (const float4*)w2_root;
        for (int p = tid; p < (DD * DD) / 4; p += 256) {
            ((float4*)Wrel)[p]  = w2r4[p];
            ((float4*)Wroot)[p] = w2o4[p];
        }
        if (tid < 128) {
            const int bsel = tid >> 6, c = tid & 63;
            float s = 0.0f;
#pragma unroll
            for (int w = 0; w < 8; ++w) s += PART[(w * 2 + bsel) * 64 + c];
            SAs[tid] = s;   // SA = adj[0,:] @ x for this batch
        }
    }
    __syncthreads();
    if (tid < 128) {
        const int bsel = tid >> 6, c = tid & 63;
        const float* X0b = X0s + bsel * 64;
        const float* SAb = SAs + bsel * 64;
        float cA = b2[c], cB = 0, cC = 0, cD = 0;
#pragma unroll 8
        for (int d = 0; d < 64; d += 2) {
            cA = fmaf(SAb[d],     Wrel[d * 64 + c],        cA);
            cB = fmaf(X0b[d],     Wroot[d * 64 + c],       cB);
            cC = fmaf(SAb[d + 1], Wrel[(d + 1) * 64 + c],  cC);
            cD = fmaf(X0b[d + 1], Wroot[(d + 1) * 64 + c], cD);
        }
        float y = fmaxf((cA + cC) + (cB + cD), 0.0f);
        SBs[tid] = y + X0b[c];  // x0 + y0
    }
    __syncthreads();
    if (tid < 4) {
        const int bsel = tid >> 1, comp = tid & 1;
        const float* SBb = SBs + bsel * 64;
        float s = bf[comp];
#pragma unroll 16
        for (int d = 0; d < 64; ++d) s = fmaf(SBb[d], wf[d * 2 + comp], s);
        out[(size_t)(b0 + bsel) * 2 + comp] = s;
    }
}

extern "C" void kernel_launch(void* const* d_in, const int* in_sizes, int n_in,
                              void* d_out, int out_size) {
    const float* adj     = (const float*)d_in[0];
    const float* vec     = (const float*)d_in[1];
    const float* w1_rel  = (const float*)d_in[2];
    const float* w1_root = (const float*)d_in[3];
    const float* b1      = (const float*)d_in[4];
    const float* w2_rel  = (const float*)d_in[5];
    const float* w2_root = (const float*)d_in[6];
    const float* b2      = (const float*)d_in[7];
    const float* wf      = (const float*)d_in[8];
    const float* bf      = (const float*)d_in[9];
    float* out = (float*)d_out;

    cudaFuncSetAttribute(gnn_fused_kernel,
                         cudaFuncAttributeMaxDynamicSharedMemorySize, SMEM_BYTES);
    gnn_fused_kernel<<<NB / 2, 256, SMEM_BYTES>>>(
        adj, vec, w1_rel, w1_root, b1, w2_rel, w2_root, b2, wf, bf, out);
}

// round 17
// speedup vs baseline: 3.4502x; 1.0485x over previous
#include <cuda_runtime.h>
#include <cstdint>

// Problem constants
#define NB 1024
#define NN 256
#define FF 63
#define DD 64

// 2 batches per CTA, 256 threads (8 warps), shared work queue, row-pair matvec
// smem byte offsets
#define OFF_WI    0        // float WI[64][128]: (wr_2c, wr_2c+1, wo_2c, wo_2c+1) per k,colpair
#define OFF_B1    32768    // float[64]
#define OFF_TV    33024    // 8 warps x 2 rows x 128 floats: interleaved (t,v); KL/KV overlay
#define OFF_JL    41216    // int[2][128]
#define OFF_VL    42240    // float[2][128]
#define OFF_CNT   43264    // int[4]
#define OFF_PART  43280    // float[8][2][64]
#define OFF_X0    47376    // float[2][64]
#define SMEM_BYTES 47888

#define OFF_SA    OFF_TV          // float[128], overlays dead tv in head
#define OFF_SB    (OFF_TV + 512)  // float[128]

__device__ __forceinline__ float4 ldcs4(const float4* p) {
    float4 v;
    asm volatile("ld.global.cs.v4.f32 {%0,%1,%2,%3}, [%4];"
                 : "=f"(v.x), "=f"(v.y), "=f"(v.z), "=f"(v.w) : "l"(p));
    return v;
}

__global__ void __launch_bounds__(256, 4) gnn_fused_kernel(
    const float* __restrict__ adj, const float* __restrict__ vec,
    const float* __restrict__ w1_rel, const float* __restrict__ w1_root,
    const float* __restrict__ b1,
    const float* __restrict__ w2_rel, const float* __restrict__ w2_root,
    const float* __restrict__ b2,
    const float* __restrict__ wf, const float* __restrict__ bf,
    float* __restrict__ out)
{
    extern __shared__ char smem[];
    float* WI   = (float*)(smem + OFF_WI);
    float* B1s  = (float*)(smem + OFF_B1);
    int*   JL   = (int*)(smem + OFF_JL);
    float* VL   = (float*)(smem + OFF_VL);
    int*   CNT  = (int*)(smem + OFF_CNT);
    float* PART = (float*)(smem + OFF_PART);
    float* X0s  = (float*)(smem + OFF_X0);
    float* SAs  = (float*)(smem + OFF_SA);
    float* SBs  = (float*)(smem + OFF_SB);

    const int tid  = threadIdx.x;
    const int lane = tid & 31;
    const int wid  = tid >> 5;
    const unsigned ltmask = (1u << lane) - 1;

    const int b0 = blockIdx.x * 2;
    const float* abf[2] = {adj + (size_t)b0 * (NN * NN),
                           adj + (size_t)(b0 + 1) * (NN * NN)};
    const float* vcf[2] = {vec + (size_t)b0 * (NN * FF),
                           vec + (size_t)(b0 + 1) * (NN * FF)};

    // ---------------- Phase A ------------------------------------------------
    // warps 6/7: issue adj row-0 loads FIRST (latency overlaps weight staging)
    float4 r0a, r0b;
    if (wid >= 6) {
        const float4* rowp0 = (const float4*)abf[wid - 6];
        r0a = ldcs4(&rowp0[lane]);
        r0b = ldcs4(&rowp0[32 + lane]);
    }
    {
        // stage w1 interleaved: WI[k*128 + 4*(n>>1) + (n&1)] = wrel, +2 = wroot
        for (int idx = tid; idx < FF * DD; idx += 256) {
            int k = idx >> 6, n = idx & 63;
            int basei = k * 128 + 4 * (n >> 1) + (n & 1);
            WI[basei]     = w1_rel[idx];
            WI[basei + 2] = w1_root[idx];
        }
        if (tid < 128) WI[63 * 128 + tid] = 0.0f;  // zero-pad k=63 row
        if (tid < 64) B1s[tid] = b1[tid];
    }
    if (wid >= 6) {  // build needed-row lists (values already in regs)
        const int bsel = wid - 6;
        float vals[8] = {r0a.x, r0a.y, r0a.z, r0a.w, r0b.x, r0b.y, r0b.z, r0b.w};
        int base = 0;
#pragma unroll
        for (int e = 0; e < 8; ++e) {
            float v = vals[e];
            unsigned m = __ballot_sync(0xffffffffu, v != 0.0f);
            if (v != 0.0f) {
                int pos = base + __popc(m & ltmask);
                int k = (e < 4) ? (4 * lane + e) : (128 + 4 * lane + (e - 4));
                if (pos < 128) {
                    JL[bsel * 128 + pos] = k;
                    VL[bsel * 128 + pos] = v;
                }
            }
            base += __popc(m);
        }
        if (lane == 0) CNT[bsel] = (base < 128) ? base : 128;
    }
    __syncthreads();

    // ---------------- Gather: shared queue, row-pair groups --------------------
    {
        const int cntA  = CNT[0];
        const int total = cntA + CNT[1];
        float* tvbase = (float*)(smem + OFF_TV) + wid * 256;  // 2 rows x 128 floats
        float px[2] = {0.0f, 0.0f}, py[2] = {0.0f, 0.0f};

        int s0 = 2 * wid;
        while (s0 < total) {
            // ---- decode + issue loads for both rows of the pair ----
            int   js[2], bsv[2], valid[2];
            float a0vs[2];
            float4 vaa[2], vbb[2];
            float vj0s[2], vj1s[2];
#pragma unroll
            for (int r = 0; r < 2; ++r) {
                const int sr = s0 + r;
                valid[r] = (sr < total);
                js[r] = 0; bsv[r] = 0; a0vs[r] = 0.0f;
                vj0s[r] = 0.0f; vj1s[r] = 0.0f;
                if (valid[r]) {
                    const int bsel = (sr < cntA) ? 0 : 1;
                    const int qi = (bsel == 0) ? sr : (128 + sr - cntA);
                    bsv[r] = bsel;
                    js[r] = JL[qi];
                    a0vs[r] = VL[qi];
                    const float4* rowp =
                        (const float4*)(abf[bsel] + (size_t)js[r] * NN);
                    vaa[r] = ldcs4(&rowp[lane]);
                    vbb[r] = ldcs4(&rowp[32 + lane]);
                    vj0s[r] = vcf[bsel][js[r] * FF + lane];
                    if (lane < 31) vj1s[r] = vcf[bsel][js[r] * FF + 32 + lane];
                }
            }

            // ---- per-row: list build + 4-wide gather + write interleaved tv ----
#pragma unroll
            for (int r = 0; r < 2; ++r) {
                if (!valid[r]) continue;
                float* slotp = tvbase + r * 128;
                int*   KL = (int*)slotp;          // 64 ints
                float* KV = slotp + 64;           // 64 floats
                const float* vcs = vcf[bsv[r]];

                float vals[8] = {vaa[r].x, vaa[r].y, vaa[r].z, vaa[r].w,
                                 vbb[r].x, vbb[r].y, vbb[r].z, vbb[r].w};
                int nk = 0;
#pragma unroll
                for (int e = 0; e < 8; ++e) {
                    float v = vals[e];
                    unsigned m = __ballot_sync(0xffffffffu, v != 0.0f);
                    if (v != 0.0f) {
                        int pos = nk + __popc(m & ltmask);
                        int k = (e < 4) ? (4 * lane + e)
                                        : (128 + 4 * lane + (e - 4));
                        if (pos < 64) { KL[pos] = k; KV[pos] = v; }
                    }
                    nk += __popc(m);
                }
                if (nk > 64) nk = 64;
                __syncwarp();

                float t0c[4] = {0, 0, 0, 0}, t1c[4] = {0, 0, 0, 0};
                int i = 0;
                for (; i + 4 <= nk; i += 4) {
                    int   k0 = KL[i],     k1 = KL[i + 1];
                    int   k2 = KL[i + 2], k3 = KL[i + 3];
                    float w0 = KV[i],     w1 = KV[i + 1];
                    float w2 = KV[i + 2], w3 = KV[i + 3];
                    const float* q0 = vcs + k0 * FF;
                    const float* q1 = vcs + k1 * FF;
                    const float* q2 = vcs + k2 * FF;
                    const float* q3 = vcs + k3 * FF;
                    float a00 = q0[lane], a10 = q1[lane];
                    float a20 = q2[lane], a30 = q3[lane];
                    float a01 = 0, a11 = 0, a21 = 0, a31 = 0;
                    if (lane < 31) {
                        a01 = q0[32 + lane]; a11 = q1[32 + lane];
                        a21 = q2[32 + lane]; a31 = q3[32 + lane];
                    }
                    t0c[0] = fmaf(w0, a00, t0c[0]);
                    t0c[1] = fmaf(w1, a10, t0c[1]);
                    t0c[2] = fmaf(w2, a20, t0c[2]);
                    t0c[3] = fmaf(w3, a30, t0c[3]);
                    t1c[0] = fmaf(w0, a01, t1c[0]);
                    t1c[1] = fmaf(w1, a11, t1c[1]);
                    t1c[2] = fmaf(w2, a21, t1c[2]);
                    t1c[3] = fmaf(w3, a31, t1c[3]);
                }
                for (; i < nk; ++i) {
                    int   k0 = KL[i];
                    float w0 = KV[i];
                    const float* q0 = vcs + k0 * FF;
                    t0c[0] = fmaf(w0, q0[lane], t0c[0]);
                    if (lane < 31) t1c[0] = fmaf(w0, q0[32 + lane], t1c[0]);
                }
                float t0 = (t0c[0] + t0c[1]) + (t0c[2] + t0c[3]);
                float t1 = (t1c[0] + t1c[1]) + (t1c[2] + t1c[3]);
                __syncwarp();   // list dead; overwrite slot with (t,v)

                float2* tvr = (float2*)slotp;
                tvr[lane]      = make_float2(t0, vj0s[r]);
                tvr[32 + lane] = (lane < 31) ? make_float2(t1, vj1s[r])
                                             : make_float2(0.0f, 0.0f);
                __syncwarp();
            }

            // ---- matvec: both rows share one pass over WI ----
            {
                const float4*  WI4 = (const float4*)WI;
                const float2*  tv0 = (const float2*)(tvbase);
                const float2*  tv1 = (const float2*)(tvbase + 128);
                float a00e = 0, a00o = 0, a01e = 0, a01o = 0;  // row0 col0/col1
                float a10e = 0, a10o = 0, a11e = 0, a11o = 0;  // row1
#pragma unroll 8
                for (int k = 0; k < 64; k += 2) {
                    float4 wA = WI4[k * 32 + lane];
                    float4 wB = WI4[(k + 1) * 32 + lane];
                    float2 p0A = tv0[k], p0B = tv0[k + 1];
                    float2 p1A = tv1[k], p1B = tv1[k + 1];
                    a00e = fmaf(p0A.x, wA.x, fmaf(p0A.y, wA.z, a00e));
                    a01e = fmaf(p0A.x, wA.y, fmaf(p0A.y, wA.w, a01e));
                    a10e = fmaf(p1A.x, wA.x, fmaf(p1A.y, wA.z, a10e));
                    a11e = fmaf(p1A.x, wA.y, fmaf(p1A.y, wA.w, a11e));
                    a00o = fmaf(p0B.x, wB.x, fmaf(p0B.y, wB.z, a00o));
                    a01o = fmaf(p0B.x, wB.y, fmaf(p0B.y, wB.w, a01o));
                    a10o = fmaf(p1B.x, wB.x, fmaf(p1B.y, wB.z, a10o));
                    a11o = fmaf(p1B.x, wB.y, fmaf(p1B.y, wB.w, a11o));
                }
                const float bb0 = B1s[2 * lane], bb1 = B1s[2 * lane + 1];
                if (valid[0]) {
                    float xv0 = fmaxf(a00e + a00o + bb0, 0.0f);
                    float xv1 = fmaxf(a01e + a01o + bb1, 0.0f);
                    px[bsv[0]] = fmaf(a0vs[0], xv0, px[bsv[0]]);
                    py[bsv[0]] = fmaf(a0vs[0], xv1, py[bsv[0]]);
                    if (js[0] == 0) {
                        X0s[bsv[0] * 64 + 2 * lane]     = xv0;
                        X0s[bsv[0] * 64 + 2 * lane + 1] = xv1;
                    }
                }
                if (valid[1]) {
                    float xv0 = fmaxf(a10e + a10o + bb0, 0.0f);
                    float xv1 = fmaxf(a11e + a11o + bb1, 0.0f);
                    px[bsv[1]] = fmaf(a0vs[1], xv0, px[bsv[1]]);
                    py[bsv[1]] = fmaf(a0vs[1], xv1, py[bsv[1]]);
                    if (js[1] == 0) {
                        X0s[bsv[1] * 64 + 2 * lane]     = xv0;
                        X0s[bsv[1] * 64 + 2 * lane + 1] = xv1;
                    }
                }
            }
            __syncwarp();   // tv reuse guard for next round
            s0 += 16;
        }
#pragma unroll
        for (int bs = 0; bs < 2; ++bs) {
            PART[(wid * 2 + bs) * 64 + 2 * lane]     = px[bs];
            PART[(wid * 2 + bs) * 64 + 2 * lane + 1] = py[bs];
        }
    }
    __syncthreads();

    // ------ Head: stage w2 interleaved into WI, then both batches' layer 2 -----
    {
        for (int idx = tid; idx < DD * DD; idx += 256) {
            int k = idx >> 6, n = idx & 63;
            int basei = k * 128 + 4 * (n >> 1) + (n & 1);
            WI[basei]     = w2_rel[idx];
            WI[basei + 2] = w2_root[idx];
        }
        if (tid < 128) {
            const int bsel = tid >> 6, c = tid & 63;
            float s = 0.0f;
#pragma unroll
            for (int w = 0; w < 8; ++w) s += PART[(w * 2 + bsel) * 64 + c];
            SAs[tid] = s;   // SA = adj[0,:] @ x for this batch
        }
    }
    __syncthreads();
    if (tid < 128) {
        const int bsel = tid >> 6, c = tid & 63;
        const float* X0b = X0s + bsel * 64;
        const float* SAb = SAs + bsel * 64;
        const float4* WI4 = (const float4*)WI;
        const int cp = c >> 1, ch = c & 1;
        float cA = b2[c], cB = 0, cC = 0, cD = 0;
#pragma unroll 8
        for (int d = 0; d < 64; d += 2) {
            float4 w0 = WI4[d * 32 + cp];
            float4 w1 = WI4[(d + 1) * 32 + cp];
            float wr0 = ch ? w0.y : w0.x, wo0 = ch ? w0.w : w0.z;
            float wr1 = ch ? w1.y : w1.x, wo1 = ch ? w1.w : w1.z;
            cA = fmaf(SAb[d],     wr0, cA);
            cB = fmaf(X0b[d],     wo0, cB);
            cC = fmaf(SAb[d + 1], wr1, cC);
            cD = fmaf(X0b[d + 1], wo1, cD);
        }
        float y = fmaxf((cA + cC) + (cB + cD), 0.0f);
        SBs[tid] = y + X0b[c];  // x0 + y0
    }
    __syncthreads();
    if (tid < 4) {
        const int bsel = tid >> 1, comp = tid & 1;
        const float* SBb = SBs + bsel * 64;
        float s = bf[comp];
#pragma unroll 16
        for (int d = 0; d < 64; ++d) s = fmaf(SBb[d], wf[d * 2 + comp], s);
        out[(size_t)(b0 + bsel) * 2 + comp] = s;
    }
}

extern "C" void kernel_launch(void* const* d_in, const int* in_sizes, int n_in,
                              void* d_out, int out_size) {
    const float* adj     = (const float*)d_in[0];
    const float* vec     = (const float*)d_in[1];
    const float* w1_rel  = (const float*)d_in[2];
    const float* w1_root = (const float*)d_in[3];
    const float* b1      = (const float*)d_in[4];
    const float* w2_rel  = (const float*)d_in[5];
    const float* w2_root = (const float*)d_in[6];
    const float* b2      = (const float*)d_in[7];
    const float* wf      = (const float*)d_in[8];
    const float* bf      = (const float*)d_in[9];
    float* out = (float*)d_out;

    cudaFuncSetAttribute(gnn_fused_kernel,
                         cudaFuncAttributeMaxDynamicSharedMemorySize, SMEM_BYTES);
    gnn_fused_kernel<<<NB / 2, 256, SMEM_BYTES>>>(
        adj, vec, w1_rel, w1_root, b1, w2_rel, w2_root, b2, wf, bf, out);
}